// round 10
// baseline (speedup 1.0000x reference)
#include <cuda_runtime.h>
#include <cuda_bf16.h>
#include <cstdint>

typedef unsigned long long ull;

#define HARD_CUT 6.5f
#define PI_F 3.14159265358979f

#define KTOT 1728            // 1600 scalar + 80 self + 48 zero pad (27*64)
#define KCH  64
#define NCH  27
#define MPAD 20096           // 157*128
#define ATOMS_PER_BLK 4

// smem stage layout (bytes, per buffer)
#define OFF_AH 0
#define OFF_AL 16384
#define OFF_BH 32768
#define OFF_BL 43008
#define STG_BYTES 53248

// ---------------- scratch (static __device__, zero-init => pad rows/cols stay 0) ----
__device__ __align__(16) __nv_bfloat16 g_env_hi[(size_t)MPAD * KTOT];
__device__ __align__(16) __nv_bfloat16 g_env_lo[(size_t)MPAD * KTOT];
__device__ __align__(16) __nv_bfloat16 g_w2h[80 * KTOT];   // B[N=80][K] K-major
__device__ __align__(16) __nv_bfloat16 g_w2l[80 * KTOT];
__device__ int g_seg[5008];                                // segment starts per atom

// ---------------- helpers ----------------
__device__ __forceinline__ void ffma2(ull &d, ull a, ull b) {
    asm("fma.rn.f32x2 %0, %1, %2, %0;" : "+l"(d) : "l"(a), "l"(b));
}
__device__ __forceinline__ ull dup2(float v) {
    ull d; asm("mov.b64 %0, {%1, %1};" : "=l"(d) : "r"(__float_as_uint(v))); return d;
}
__device__ __forceinline__ float2 unpack2(ull v) {
    return make_float2(__uint_as_float((unsigned)(v & 0xffffffffull)),
                       __uint_as_float((unsigned)(v >> 32)));
}
__device__ __forceinline__ int lower_bound_i(const int* __restrict__ arr, int n, int val) {
    int lo = 0, hi = n;
    while (lo < hi) { int mid = (lo + hi) >> 1; if (arr[mid] < val) lo = mid + 1; else hi = mid; }
    return lo;
}
__device__ __forceinline__ uint32_t smem_u32(const void* p) {
    uint32_t a;
    asm("{ .reg .u64 t; cvta.to.shared.u64 t, %1; cvt.u32.u64 %0, t; }" : "=r"(a) : "l"(p));
    return a;
}
__device__ __forceinline__ void ldsm4(unsigned* r, uint32_t addr) {
    asm volatile("ldmatrix.sync.aligned.m8n8.x4.shared.b16 {%0,%1,%2,%3}, [%4];"
        : "=r"(r[0]), "=r"(r[1]), "=r"(r[2]), "=r"(r[3]) : "r"(addr));
}
__device__ __forceinline__ void ldsm2(unsigned* r, uint32_t addr) {
    asm volatile("ldmatrix.sync.aligned.m8n8.x2.shared.b16 {%0,%1}, [%2];"
        : "=r"(r[0]), "=r"(r[1]) : "r"(addr));
}
__device__ __forceinline__ void mma16816(float* d, const unsigned* a, const unsigned* b) {
    asm volatile("mma.sync.aligned.m16n8k16.row.col.f32.bf16.bf16.f32 "
        "{%0,%1,%2,%3}, {%4,%5,%6,%7}, {%8,%9}, {%0,%1,%2,%3};"
        : "+f"(d[0]), "+f"(d[1]), "+f"(d[2]), "+f"(d[3])
        : "r"(a[0]), "r"(a[1]), "r"(a[2]), "r"(a[3]), "r"(b[0]), "r"(b[1]));
}
#define CP16(dst, src)  asm volatile("cp.async.cg.shared.global [%0], [%1], 16;" :: "r"(dst), "l"(src) : "memory")
#define CP_COMMIT()     asm volatile("cp.async.commit_group;" ::: "memory")
#define CP_WAIT1()      asm volatile("cp.async.wait_group 1;" ::: "memory")
#define CP_WAIT0()      asm volatile("cp.async.wait_group 0;" ::: "memory")

// ---------------- K0a: W2 -> bf16 hi/lo, [80 o][1728 k] K-major ----------------
__global__ void build_w_kernel(const float* __restrict__ iw, const float* __restrict__ selfw) {
    int idx = blockIdx.x * blockDim.x + threadIdx.x;
    if (idx >= 80 * KTOT) return;
    int o = idx / KTOT, k = idx % KTOT;
    float v = 0.0f;
    if (k < 1600)      { int s = k / 80, f = k % 80; v = iw[s * 6400 + o * 80 + f]; }
    else if (k < 1680) { v = selfw[o * 80 + (k - 1600)]; }
    __nv_bfloat16 h = __float2bfloat16(v);
    __nv_bfloat16 l = __float2bfloat16(v - __bfloat162float(h));
    g_w2h[idx] = h;
    g_w2l[idx] = l;
}

// ---------------- K0b: segment boundaries (one binary search per atom) ----------------
__global__ void seg_kernel(const int* __restrict__ pf, int n_pairs, int n_atoms) {
    int a = blockIdx.x * blockDim.x + threadIdx.x;
    if (a <= n_atoms) g_seg[a] = lower_bound_i(pf, n_pairs, a);
}

// ---------------- K1: segmented envsum -> bf16 hi/lo env ----------------
// 4 atoms/block, 320 threads, global 16-pair chunks.
// Producer: lane j==0 per pair computes inv/cut/channel-weights (RCP+COS, done
// during prefetch overlap); all 20 lanes do exactly 1 EX2 each (sense phase).
// Consumer: 2cs x 10f f32x2 tile; flushes at uniform atom boundaries.
__device__ __forceinline__ void flush_acc(ull acc[2][5], int a, int cs0, int f0) {
    int c  = cs0 / 20;
    int s0 = cs0 % 20;
    size_t rbase = (size_t)(a * 4 + c) * KTOT;
    #pragma unroll
    for (int i = 0; i < 2; i++) {
        size_t cb = rbase + (s0 + i) * 80 + f0;
        #pragma unroll
        for (int u = 0; u < 5; u++) {
            float2 v = unpack2(acc[i][u]);
            __nv_bfloat16 h0 = __float2bfloat16(v.x);
            __nv_bfloat16 l0 = __float2bfloat16(v.x - __bfloat162float(h0));
            __nv_bfloat16 h1 = __float2bfloat16(v.y);
            __nv_bfloat16 l1 = __float2bfloat16(v.y - __bfloat162float(h1));
            __nv_bfloat162 hh; hh.x = h0; hh.y = h1;
            __nv_bfloat162 ll; ll.x = l0; ll.y = l1;
            *(__nv_bfloat162*)&g_env_hi[cb + 2 * u] = hh;
            *(__nv_bfloat162*)&g_env_lo[cb + 2 * u] = ll;
            acc[i][u] = 0ull;
        }
    }
}

__global__ __launch_bounds__(320) void envsum_kernel(
    const float* __restrict__ feat, const float* __restrict__ dist,
    const float* __restrict__ coord, const float* __restrict__ mu,
    const float* __restrict__ sigma, const int* __restrict__ ps)
{
    __shared__ float s_inv[16];
    __shared__ __align__(16) float s_w[16][4];
    __shared__ float s_sense[16][20];
    __shared__ __align__(16) float s_feat[16][80];

    int a0  = blockIdx.x * ATOMS_PER_BLK;
    int tid = threadIdx.x;

    int segs[ATOMS_PER_BLK + 1];
    #pragma unroll
    for (int i = 0; i <= ATOMS_PER_BLK; i++) segs[i] = g_seg[a0 + i];
    int start  = segs[0];
    int endall = segs[ATOMS_PER_BLK];

    int csg = tid >> 3;  int cs0 = csg * 2;
    int fg  = tid & 7;   int f0  = fg * 10;
    int ci  = cs0 / 20;  int s0i = cs0 % 20;   // both senses in same channel (cs0 even)

    int pp = tid / 20;
    int j  = tid - pp * 20;
    float muj = mu[j];
    float isj = 1.0f / sigma[j];

    ull acc[2][5];
    #pragma unroll
    for (int i = 0; i < 2; i++)
        #pragma unroll
        for (int u = 0; u < 5; u++) acc[i][u] = 0ull;

    int nchunk = (endall - start + 15) >> 4;

    // register prefetch buffers; j==0 also pre-computes per-pair scalars
    float4 nf = make_float4(0.f, 0.f, 0.f, 0.f);
    float p_inv = 0.f;
    float4 p_w  = make_float4(0.f, 0.f, 0.f, 0.f);
    int have = 0;
    if (nchunk > 0 && start + pp < endall) {
        int p = start + pp;
        if (j == 0) {
            float d = dist[p];
            float x = coord[3 * p], y = coord[3 * p + 1], z = coord[3 * p + 2];
            float inv = 1.0f / d;
            float cut = (d < HARD_CUT) ? 0.5f * (__cosf(PI_F * d * (1.0f / HARD_CUT)) + 1.0f) : 0.0f;
            p_inv = inv;
            p_w   = make_float4(cut, cut * x * inv, cut * y * inv, cut * z * inv);
        }
        int r = ps[p]; nf = ((const float4*)feat)[r * 20 + j];
        have = 1;
    }

    int a_cur = a0;
    int bnd   = segs[1];

    for (int ch = 0; ch < nchunk; ch++) {
        __syncthreads();                       // A: previous consume done
        if (have) {
            if (j == 0) { s_inv[pp] = p_inv; *(float4*)&s_w[pp][0] = p_w; }
            *(float4*)&s_feat[pp][j * 4] = nf;
        }
        int p0  = start + ch * 16;
        int cnt = min(16, endall - p0);
        __syncthreads();                       // B: s_inv visible

        if (have) {
            float inv = s_inv[pp];
            float z   = (inv - muj) * isj;
            s_sense[pp][j] = __expf(-0.5f * z * z);
        }

        // prefetch chunk ch+1 (LDG + j0's RCP/COS overlap the consume loop)
        have = 0;
        if (ch + 1 < nchunk) {
            int p = start + (ch + 1) * 16 + pp;
            if (p < endall) {
                if (j == 0) {
                    float d = dist[p];
                    float x = coord[3 * p], y = coord[3 * p + 1], z = coord[3 * p + 2];
                    float inv = 1.0f / d;
                    float cut = (d < HARD_CUT) ? 0.5f * (__cosf(PI_F * d * (1.0f / HARD_CUT)) + 1.0f) : 0.0f;
                    p_inv = inv;
                    p_w   = make_float4(cut, cut * x * inv, cut * y * inv, cut * z * inv);
                }
                int r = ps[p]; nf = ((const float4*)feat)[r * 20 + j];
                have = 1;
            }
        }
        __syncthreads();                       // C: senses ready

        for (int p = 0; p < cnt; p++) {
            int gp = p0 + p;
            while (gp == bnd && a_cur < a0 + ATOMS_PER_BLK - 1) {
                flush_acc(acc, a_cur, cs0, f0);
                a_cur++;
                bnd = segs[a_cur - a0 + 1];
            }
            float2 sn = *(const float2*)&s_sense[p][s0i];
            float  wc = s_w[p][ci];
            ull c0d = dup2(sn.x * wc);
            ull c1d = dup2(sn.y * wc);
            #pragma unroll
            for (int u = 0; u < 5; u++) {
                ull fv = *(const ull*)&s_feat[p][f0 + 2 * u];
                ffma2(acc[0][u], c0d, fv);
                ffma2(acc[1][u], c1d, fv);
            }
        }
    }

    // flush remaining atoms (covers empty trailing segments too)
    for (int a = a_cur; a < a0 + ATOMS_PER_BLK; a++)
        flush_acc(acc, a, cs0, f0);

    // self-interaction rows: env[(a,c), 1600+f] = (c==0) ? feat[a,f] : 0
    {
        int c2 = tid / 80;   // 0..3
        int f  = tid % 80;
        #pragma unroll
        for (int ai = 0; ai < ATOMS_PER_BLK; ai++) {
            int a = a0 + ai;
            float v = (c2 == 0) ? feat[a * 80 + f] : 0.0f;
            __nv_bfloat16 h = __float2bfloat16(v);
            __nv_bfloat16 l = __float2bfloat16(v - __bfloat162float(h));
            size_t off = (size_t)(a * 4 + c2) * KTOT + 1600 + f;
            g_env_hi[off] = h;
            g_env_lo[off] = l;
        }
    }
}

// ---------------- K2: bf16-split GEMM via mma.sync + fused epilogue ----------------
// 256 threads = 8 warps: warp (wid>>1) owns 32 M-rows, (wid&1) owns 40 N-cols.
// launch_bounds(256,2): cap regs at 128 so 2 CTAs/SM co-reside (2x104KB smem fits).
__device__ __forceinline__ void load_stage(uint32_t sstage, int m0, int kc, int tid) {
    #pragma unroll
    for (int i = 0; i < 4; i++) {
        int u = tid + i * 256;                 // 1024: 128 rows x 8 segs
        int r = u >> 3, sg = u & 7;
        uint32_t so = (uint32_t)(r * 128 + ((sg ^ (r & 7)) * 16));
        const char* gh = (const char*)(g_env_hi + (size_t)(m0 + r) * KTOT + kc) + sg * 16;
        const char* gl = (const char*)(g_env_lo + (size_t)(m0 + r) * KTOT + kc) + sg * 16;
        CP16(sstage + OFF_AH + so, gh);
        CP16(sstage + OFF_AL + so, gl);
    }
    #pragma unroll
    for (int i = 0; i < 3; i++) {
        int u = tid + i * 256;                 // 640: 80 rows x 8 segs
        if (u < 640) {
            int r = u >> 3, sg = u & 7;
            uint32_t so = (uint32_t)(r * 128 + ((sg ^ (r & 7)) * 16));
            const char* gh = (const char*)(g_w2h + (size_t)r * KTOT + kc) + sg * 16;
            const char* gl = (const char*)(g_w2l + (size_t)r * KTOT + kc) + sg * 16;
            CP16(sstage + OFF_BH + so, gh);
            CP16(sstage + OFF_BL + so, gl);
        }
    }
}

__global__ __launch_bounds__(256, 2)
void gemm_kernel(const float* __restrict__ selfb, const float* __restrict__ vecs,
                 float* __restrict__ out, int n_atoms)
{
    extern __shared__ __align__(1024) char smem[];
    uint32_t sb = smem_u32(smem);
    int tid  = threadIdx.x;
    int lane = tid & 31;
    int wid  = tid >> 5;
    int m0   = blockIdx.x * 128;
    int m0w  = (wid >> 1) * 32;
    int n0w  = (wid & 1) * 40;

    int rA_loc = (lane & 7) + ((lane >> 3) & 1) * 8;
    uint32_t rowA0 = (uint32_t)((m0w + rA_loc) * 128);
    uint32_t rowA1 = rowA0 + 16 * 128;
    int rB_loc = (lane & 7) + ((lane >> 4) & 1) * 8;
    uint32_t rowB0 = (uint32_t)((n0w + rB_loc) * 128);
    uint32_t rowB1 = rowB0 + 16 * 128;
    uint32_t rowB2 = (uint32_t)((n0w + 32 + (lane & 7)) * 128);

    float acc[2][5][4];
    #pragma unroll
    for (int mt = 0; mt < 2; mt++)
        #pragma unroll
        for (int nt = 0; nt < 5; nt++)
            #pragma unroll
            for (int q = 0; q < 4; q++) acc[mt][nt][q] = 0.0f;

    load_stage(sb, m0, 0, tid);              CP_COMMIT();
    load_stage(sb + STG_BYTES, m0, KCH, tid); CP_COMMIT();

    for (int c = 0; c < NCH; c++) {
        if (c < NCH - 1) CP_WAIT1(); else CP_WAIT0();
        __syncthreads();

        uint32_t st  = sb + (uint32_t)((c & 1) * STG_BYTES);
        uint32_t sAH = st + OFF_AH, sAL = st + OFF_AL;
        uint32_t sBH = st + OFF_BH, sBL = st + OFF_BL;

        #pragma unroll
        for (int ks = 0; ks < 4; ks++) {
            uint32_t swA = (uint32_t)((((ks * 2) + (lane >> 4)) ^ (lane & 7)) * 16);
            uint32_t swB = (uint32_t)((((ks * 2) + ((lane >> 3) & 1)) ^ (lane & 7)) * 16);
            unsigned aH[2][4], aL[2][4], bH[10], bL[10];
            ldsm4(aH[0], sAH + rowA0 + swA);
            ldsm4(aH[1], sAH + rowA1 + swA);
            ldsm4(aL[0], sAL + rowA0 + swA);
            ldsm4(aL[1], sAL + rowA1 + swA);
            ldsm4(bH + 0, sBH + rowB0 + swB);
            ldsm4(bH + 4, sBH + rowB1 + swB);
            ldsm2(bH + 8, sBH + rowB2 + swB);
            ldsm4(bL + 0, sBL + rowB0 + swB);
            ldsm4(bL + 4, sBL + rowB1 + swB);
            ldsm2(bL + 8, sBL + rowB2 + swB);
            #pragma unroll
            for (int mt = 0; mt < 2; mt++)
                #pragma unroll
                for (int nt = 0; nt < 5; nt++) {
                    mma16816(acc[mt][nt], aH[mt], bH + 2 * nt);
                    mma16816(acc[mt][nt], aL[mt], bH + 2 * nt);
                    mma16816(acc[mt][nt], aH[mt], bL + 2 * nt);
                }
        }
        __syncthreads();
        if (c + 2 < NCH) { load_stage(sb + (uint32_t)((c & 1) * STG_BYTES), m0, (c + 2) * KCH, tid); CP_COMMIT(); }
    }

    // write accumulators to smem C[128][80]
    float* C = (float*)smem;
    int grp  = lane >> 2;
    int col0 = (lane & 3) * 2;
    #pragma unroll
    for (int mt = 0; mt < 2; mt++) {
        int r0 = m0w + mt * 16 + grp;
        #pragma unroll
        for (int nt = 0; nt < 5; nt++) {
            int cc = n0w + nt * 8 + col0;
            *(float2*)&C[r0 * 80 + cc]       = make_float2(acc[mt][nt][0], acc[mt][nt][1]);
            *(float2*)&C[(r0 + 8) * 80 + cc] = make_float2(acc[mt][nt][2], acc[mt][nt][3]);
        }
    }
    __syncthreads();

    #pragma unroll
    for (int u = tid; u < 2560; u += 256) {
        int al = u / 80, o = u % 80;
        int a = (m0 >> 2) + al;
        if (a < n_atoms) {
            float s0 = C[(al * 4 + 0) * 80 + o];
            float x  = C[(al * 4 + 1) * 80 + o];
            float y  = C[(al * 4 + 2) * 80 + o];
            float z  = C[(al * 4 + 3) * 80 + o];
            out[a * 80 + o] = s0 + selfb[o]
                + vecs[o] * sqrtf(fmaf(x, x, fmaf(y, y, z * z)) + 1e-30f);
        }
    }
}

// ---------------- launch ----------------
extern "C" void kernel_launch(void* const* d_in, const int* in_sizes, int n_in,
                              void* d_out, int out_size) {
    const float* feat  = (const float*)d_in[0];
    const float* dist  = (const float*)d_in[1];
    const float* coord = (const float*)d_in[2];
    const float* iw    = (const float*)d_in[3];
    const float* selfw = (const float*)d_in[4];
    const float* selfb = (const float*)d_in[5];
    const float* vecs  = (const float*)d_in[6];
    const float* mu    = (const float*)d_in[7];
    const float* sigma = (const float*)d_in[8];
    const int*   pf    = (const int*)d_in[9];
    const int*   ps    = (const int*)d_in[10];
    int n_pairs = in_sizes[9];
    int n_atoms = in_sizes[0] / 80;
    float* out = (float*)d_out;

    static int smem_set = 0;
    if (!smem_set) {
        cudaFuncSetAttribute(gemm_kernel, cudaFuncAttributeMaxDynamicSharedMemorySize,
                             2 * STG_BYTES);
        smem_set = 1;
    }

    build_w_kernel<<<(80 * KTOT + 255) / 256, 256>>>(iw, selfw);
    seg_kernel<<<(n_atoms + 256) / 256, 256>>>(pf, n_pairs, n_atoms);
    envsum_kernel<<<n_atoms / ATOMS_PER_BLK, 320>>>(feat, dist, coord, mu, sigma, ps);
    int mtiles = (n_atoms * 4 + 127) / 128;
    gemm_kernel<<<mtiles, 256, 2 * STG_BYTES>>>(selfb, vecs, out, n_atoms);
}

// round 11
// speedup vs baseline: 1.1702x; 1.1702x over previous
#include <cuda_runtime.h>
#include <cuda_bf16.h>
#include <cstdint>

typedef unsigned long long ull;

#define HARD_CUT 6.5f
#define PI_F 3.14159265358979f

#define KTOT 1728            // 1600 scalar + 80 self + 48 zero pad (27*64)
#define KCH  64
#define NCH  27
#define MPAD 20096           // 314*64
#define ATOMS_PER_BLK 4

// smem stage layout (bytes, per buffer) — BM=64 tiles
#define BM64   64
#define OFF_AH 0
#define OFF_AL 8192
#define OFF_BH 16384
#define OFF_BL 26624
#define STG_BYTES 36864

// ---------------- scratch (static __device__, zero-init => pad rows/cols stay 0) ----
__device__ __align__(16) __nv_bfloat16 g_env_hi[(size_t)MPAD * KTOT];
__device__ __align__(16) __nv_bfloat16 g_env_lo[(size_t)MPAD * KTOT];
__device__ __align__(16) __nv_bfloat16 g_w2h[80 * KTOT];   // B[N=80][K] K-major
__device__ __align__(16) __nv_bfloat16 g_w2l[80 * KTOT];
__device__ int g_seg[5008];                                // segment starts per atom

// ---------------- helpers ----------------
__device__ __forceinline__ void ffma2(ull &d, ull a, ull b) {
    asm("fma.rn.f32x2 %0, %1, %2, %0;" : "+l"(d) : "l"(a), "l"(b));
}
__device__ __forceinline__ ull dup2(float v) {
    ull d; asm("mov.b64 %0, {%1, %1};" : "=l"(d) : "r"(__float_as_uint(v))); return d;
}
__device__ __forceinline__ float2 unpack2(ull v) {
    return make_float2(__uint_as_float((unsigned)(v & 0xffffffffull)),
                       __uint_as_float((unsigned)(v >> 32)));
}
__device__ __forceinline__ int lower_bound_i(const int* __restrict__ arr, int n, int val) {
    int lo = 0, hi = n;
    while (lo < hi) { int mid = (lo + hi) >> 1; if (arr[mid] < val) lo = mid + 1; else hi = mid; }
    return lo;
}
__device__ __forceinline__ uint32_t smem_u32(const void* p) {
    uint32_t a;
    asm("{ .reg .u64 t; cvta.to.shared.u64 t, %1; cvt.u32.u64 %0, t; }" : "=r"(a) : "l"(p));
    return a;
}
__device__ __forceinline__ void ldsm4(unsigned* r, uint32_t addr) {
    asm volatile("ldmatrix.sync.aligned.m8n8.x4.shared.b16 {%0,%1,%2,%3}, [%4];"
        : "=r"(r[0]), "=r"(r[1]), "=r"(r[2]), "=r"(r[3]) : "r"(addr));
}
__device__ __forceinline__ void ldsm2(unsigned* r, uint32_t addr) {
    asm volatile("ldmatrix.sync.aligned.m8n8.x2.shared.b16 {%0,%1}, [%2];"
        : "=r"(r[0]), "=r"(r[1]) : "r"(addr));
}
__device__ __forceinline__ void mma16816(float* d, const unsigned* a, const unsigned* b) {
    asm volatile("mma.sync.aligned.m16n8k16.row.col.f32.bf16.bf16.f32 "
        "{%0,%1,%2,%3}, {%4,%5,%6,%7}, {%8,%9}, {%0,%1,%2,%3};"
        : "+f"(d[0]), "+f"(d[1]), "+f"(d[2]), "+f"(d[3])
        : "r"(a[0]), "r"(a[1]), "r"(a[2]), "r"(a[3]), "r"(b[0]), "r"(b[1]));
}
#define CP16(dst, src)  asm volatile("cp.async.cg.shared.global [%0], [%1], 16;" :: "r"(dst), "l"(src) : "memory")
#define CP_COMMIT()     asm volatile("cp.async.commit_group;" ::: "memory")
#define CP_WAIT1()      asm volatile("cp.async.wait_group 1;" ::: "memory")
#define CP_WAIT0()      asm volatile("cp.async.wait_group 0;" ::: "memory")

// ---------------- K0a: W2 -> bf16 hi/lo, [80 o][1728 k] K-major ----------------
__global__ void build_w_kernel(const float* __restrict__ iw, const float* __restrict__ selfw) {
    int idx = blockIdx.x * blockDim.x + threadIdx.x;
    if (idx >= 80 * KTOT) return;
    int o = idx / KTOT, k = idx % KTOT;
    float v = 0.0f;
    if (k < 1600)      { int s = k / 80, f = k % 80; v = iw[s * 6400 + o * 80 + f]; }
    else if (k < 1680) { v = selfw[o * 80 + (k - 1600)]; }
    __nv_bfloat16 h = __float2bfloat16(v);
    __nv_bfloat16 l = __float2bfloat16(v - __bfloat162float(h));
    g_w2h[idx] = h;
    g_w2l[idx] = l;
}

// ---------------- K0b: segment boundaries (one binary search per atom) ----------------
__global__ void seg_kernel(const int* __restrict__ pf, int n_pairs, int n_atoms) {
    int a = blockIdx.x * blockDim.x + threadIdx.x;
    if (a <= n_atoms) g_seg[a] = lower_bound_i(pf, n_pairs, a);
}

// ---------------- K1: segmented envsum (R8 version — known-good) ----------------
__device__ __forceinline__ void flush_acc(ull acc[2][5], int a, int cs0, int f0) {
    int c  = cs0 / 20;
    int s0 = cs0 % 20;
    size_t rbase = (size_t)(a * 4 + c) * KTOT;
    #pragma unroll
    for (int i = 0; i < 2; i++) {
        size_t cb = rbase + (s0 + i) * 80 + f0;
        #pragma unroll
        for (int u = 0; u < 5; u++) {
            float2 v = unpack2(acc[i][u]);
            __nv_bfloat16 h0 = __float2bfloat16(v.x);
            __nv_bfloat16 l0 = __float2bfloat16(v.x - __bfloat162float(h0));
            __nv_bfloat16 h1 = __float2bfloat16(v.y);
            __nv_bfloat16 l1 = __float2bfloat16(v.y - __bfloat162float(h1));
            __nv_bfloat162 hh; hh.x = h0; hh.y = h1;
            __nv_bfloat162 ll; ll.x = l0; ll.y = l1;
            *(__nv_bfloat162*)&g_env_hi[cb + 2 * u] = hh;
            *(__nv_bfloat162*)&g_env_lo[cb + 2 * u] = ll;
            acc[i][u] = 0ull;
        }
    }
}

__global__ __launch_bounds__(320) void envsum_kernel(
    const float* __restrict__ feat, const float* __restrict__ dist,
    const float* __restrict__ coord, const float* __restrict__ mu,
    const float* __restrict__ sigma, const int* __restrict__ ps)
{
    __shared__ __align__(16) float s_coef[16][80];
    __shared__ __align__(16) float s_feat[16][80];

    int a0  = blockIdx.x * ATOMS_PER_BLK;
    int tid = threadIdx.x;

    int segs[ATOMS_PER_BLK + 1];
    #pragma unroll
    for (int i = 0; i <= ATOMS_PER_BLK; i++) segs[i] = g_seg[a0 + i];
    int start  = segs[0];
    int endall = segs[ATOMS_PER_BLK];

    int csg = tid >> 3;  int cs0 = csg * 2;
    int fg  = tid & 7;   int f0  = fg * 10;

    int pp = tid / 20;
    int j  = tid - pp * 20;
    float muj = mu[j];
    float isj = 1.0f / sigma[j];

    ull acc[2][5];
    #pragma unroll
    for (int i = 0; i < 2; i++)
        #pragma unroll
        for (int u = 0; u < 5; u++) acc[i][u] = 0ull;

    int nchunk = (endall - start + 15) >> 4;

    float nd = 1.0f, nx = 0.f, ny = 0.f, nz = 0.f;
    float4 nf = make_float4(0.f, 0.f, 0.f, 0.f);
    int have = 0;
    if (nchunk > 0 && start + pp < endall) {
        int p = start + pp;
        nd = dist[p]; nx = coord[3 * p]; ny = coord[3 * p + 1]; nz = coord[3 * p + 2];
        int r = ps[p]; nf = ((const float4*)feat)[r * 20 + j];
        have = 1;
    }

    int a_cur = a0;
    int bnd   = segs[1];

    for (int ch = 0; ch < nchunk; ch++) {
        __syncthreads();
        if (have) {
            float d   = nd;
            float inv = 1.0f / d;
            float cut = (d < HARD_CUT) ? 0.5f * (__cosf(PI_F * d * (1.0f / HARD_CUT)) + 1.0f) : 0.0f;
            float z   = (inv - muj) * isj;
            float e   = __expf(-0.5f * z * z) * cut;
            s_coef[pp][j]      = e;
            s_coef[pp][20 + j] = e * nx * inv;
            s_coef[pp][40 + j] = e * ny * inv;
            s_coef[pp][60 + j] = e * nz * inv;
            *(float4*)&s_feat[pp][j * 4] = nf;
        }
        int p0  = start + ch * 16;
        int cnt = min(16, endall - p0);
        __syncthreads();

        have = 0;
        if (ch + 1 < nchunk) {
            int p = start + (ch + 1) * 16 + pp;
            if (p < endall) {
                nd = dist[p]; nx = coord[3 * p]; ny = coord[3 * p + 1]; nz = coord[3 * p + 2];
                int r = ps[p]; nf = ((const float4*)feat)[r * 20 + j];
                have = 1;
            }
        }

        for (int p = 0; p < cnt; p++) {
            int gp = p0 + p;
            while (gp == bnd && a_cur < a0 + ATOMS_PER_BLK - 1) {
                flush_acc(acc, a_cur, cs0, f0);
                a_cur++;
                bnd = segs[a_cur - a0 + 1];
            }
            float2 cf = *(const float2*)&s_coef[p][cs0];
            ull c0d = dup2(cf.x);
            ull c1d = dup2(cf.y);
            #pragma unroll
            for (int u = 0; u < 5; u++) {
                ull fv = *(const ull*)&s_feat[p][f0 + 2 * u];
                ffma2(acc[0][u], c0d, fv);
                ffma2(acc[1][u], c1d, fv);
            }
        }
    }

    for (int a = a_cur; a < a0 + ATOMS_PER_BLK; a++)
        flush_acc(acc, a, cs0, f0);

    {
        int c2 = tid / 80;   // 0..3
        int f  = tid % 80;
        #pragma unroll
        for (int ai = 0; ai < ATOMS_PER_BLK; ai++) {
            int a = a0 + ai;
            float v = (c2 == 0) ? feat[a * 80 + f] : 0.0f;
            __nv_bfloat16 h = __float2bfloat16(v);
            __nv_bfloat16 l = __float2bfloat16(v - __bfloat162float(h));
            size_t off = (size_t)(a * 4 + c2) * KTOT + 1600 + f;
            g_env_hi[off] = h;
            g_env_lo[off] = l;
        }
    }
}

// ---------------- K2: bf16-split GEMM, BM=64, 2 CTAs/SM ----------------
// 256 threads = 8 warps: warp (wid>>1) owns 16 M-rows, (wid&1) owns 40 N-cols.
// Stage: A_hi 8K | A_lo 8K | B_hi 10K | B_lo 10K, x2 buffers = 73.7KB total.
__device__ __forceinline__ void load_stage(uint32_t sstage, int m0, int kc, int tid) {
    #pragma unroll
    for (int i = 0; i < 2; i++) {
        int u = tid + i * 256;                 // 512: 64 rows x 8 segs
        int r = u >> 3, sg = u & 7;
        uint32_t so = (uint32_t)(r * 128 + ((sg ^ (r & 7)) * 16));
        const char* gh = (const char*)(g_env_hi + (size_t)(m0 + r) * KTOT + kc) + sg * 16;
        const char* gl = (const char*)(g_env_lo + (size_t)(m0 + r) * KTOT + kc) + sg * 16;
        CP16(sstage + OFF_AH + so, gh);
        CP16(sstage + OFF_AL + so, gl);
    }
    #pragma unroll
    for (int i = 0; i < 3; i++) {
        int u = tid + i * 256;                 // 640: 80 rows x 8 segs
        if (u < 640) {
            int r = u >> 3, sg = u & 7;
            uint32_t so = (uint32_t)(r * 128 + ((sg ^ (r & 7)) * 16));
            const char* gh = (const char*)(g_w2h + (size_t)r * KTOT + kc) + sg * 16;
            const char* gl = (const char*)(g_w2l + (size_t)r * KTOT + kc) + sg * 16;
            CP16(sstage + OFF_BH + so, gh);
            CP16(sstage + OFF_BL + so, gl);
        }
    }
}

__global__ __launch_bounds__(256, 2)
void gemm_kernel(const float* __restrict__ selfb, const float* __restrict__ vecs,
                 float* __restrict__ out, int n_atoms)
{
    extern __shared__ __align__(1024) char smem[];
    uint32_t sb = smem_u32(smem);
    int tid  = threadIdx.x;
    int lane = tid & 31;
    int wid  = tid >> 5;
    int m0   = blockIdx.x * BM64;
    int m0w  = (wid >> 1) * 16;
    int n0w  = (wid & 1) * 40;

    int rA_loc = (lane & 7) + ((lane >> 3) & 1) * 8;
    uint32_t rowA0 = (uint32_t)((m0w + rA_loc) * 128);
    int rB_loc = (lane & 7) + ((lane >> 4) & 1) * 8;
    uint32_t rowB0 = (uint32_t)((n0w + rB_loc) * 128);
    uint32_t rowB1 = rowB0 + 16 * 128;
    uint32_t rowB2 = (uint32_t)((n0w + 32 + (lane & 7)) * 128);

    float acc[5][4];
    #pragma unroll
    for (int nt = 0; nt < 5; nt++)
        #pragma unroll
        for (int q = 0; q < 4; q++) acc[nt][q] = 0.0f;

    load_stage(sb, m0, 0, tid);               CP_COMMIT();
    load_stage(sb + STG_BYTES, m0, KCH, tid); CP_COMMIT();

    for (int c = 0; c < NCH; c++) {
        if (c < NCH - 1) CP_WAIT1(); else CP_WAIT0();
        __syncthreads();

        uint32_t st  = sb + (uint32_t)((c & 1) * STG_BYTES);
        uint32_t sAH = st + OFF_AH, sAL = st + OFF_AL;
        uint32_t sBH = st + OFF_BH, sBL = st + OFF_BL;

        #pragma unroll
        for (int ks = 0; ks < 4; ks++) {
            uint32_t swA = (uint32_t)((((ks * 2) + (lane >> 4)) ^ (lane & 7)) * 16);
            uint32_t swB = (uint32_t)((((ks * 2) + ((lane >> 3) & 1)) ^ (lane & 7)) * 16);
            unsigned aH[4], aL[4], bH[10], bL[10];
            ldsm4(aH, sAH + rowA0 + swA);
            ldsm4(aL, sAL + rowA0 + swA);
            ldsm4(bH + 0, sBH + rowB0 + swB);
            ldsm4(bH + 4, sBH + rowB1 + swB);
            ldsm2(bH + 8, sBH + rowB2 + swB);
            ldsm4(bL + 0, sBL + rowB0 + swB);
            ldsm4(bL + 4, sBL + rowB1 + swB);
            ldsm2(bL + 8, sBL + rowB2 + swB);
            #pragma unroll
            for (int nt = 0; nt < 5; nt++) {
                mma16816(acc[nt], aH, bH + 2 * nt);
                mma16816(acc[nt], aL, bH + 2 * nt);
                mma16816(acc[nt], aH, bL + 2 * nt);
            }
        }
        __syncthreads();
        if (c + 2 < NCH) { load_stage(sb + (uint32_t)((c & 1) * STG_BYTES), m0, (c + 2) * KCH, tid); CP_COMMIT(); }
    }

    // write accumulators to smem C[64][80]
    float* C = (float*)smem;
    int grp  = lane >> 2;
    int col0 = (lane & 3) * 2;
    {
        int r0 = m0w + grp;
        #pragma unroll
        for (int nt = 0; nt < 5; nt++) {
            int cc = n0w + nt * 8 + col0;
            *(float2*)&C[r0 * 80 + cc]       = make_float2(acc[nt][0], acc[nt][1]);
            *(float2*)&C[(r0 + 8) * 80 + cc] = make_float2(acc[nt][2], acc[nt][3]);
        }
    }
    __syncthreads();

    #pragma unroll
    for (int u = tid; u < 1280; u += 256) {
        int al = u / 80, o = u % 80;
        int a = (m0 >> 2) + al;
        if (a < n_atoms) {
            float s0 = C[(al * 4 + 0) * 80 + o];
            float x  = C[(al * 4 + 1) * 80 + o];
            float y  = C[(al * 4 + 2) * 80 + o];
            float z  = C[(al * 4 + 3) * 80 + o];
            out[a * 80 + o] = s0 + selfb[o]
                + vecs[o] * sqrtf(fmaf(x, x, fmaf(y, y, z * z)) + 1e-30f);
        }
    }
}

// ---------------- launch ----------------
extern "C" void kernel_launch(void* const* d_in, const int* in_sizes, int n_in,
                              void* d_out, int out_size) {
    const float* feat  = (const float*)d_in[0];
    const float* dist  = (const float*)d_in[1];
    const float* coord = (const float*)d_in[2];
    const float* iw    = (const float*)d_in[3];
    const float* selfw = (const float*)d_in[4];
    const float* selfb = (const float*)d_in[5];
    const float* vecs  = (const float*)d_in[6];
    const float* mu    = (const float*)d_in[7];
    const float* sigma = (const float*)d_in[8];
    const int*   pf    = (const int*)d_in[9];
    const int*   ps    = (const int*)d_in[10];
    int n_pairs = in_sizes[9];
    int n_atoms = in_sizes[0] / 80;
    float* out = (float*)d_out;

    static int smem_set = 0;
    if (!smem_set) {
        cudaFuncSetAttribute(gemm_kernel, cudaFuncAttributeMaxDynamicSharedMemorySize,
                             2 * STG_BYTES);
        smem_set = 1;
    }

    build_w_kernel<<<(80 * KTOT + 255) / 256, 256>>>(iw, selfw);
    seg_kernel<<<(n_atoms + 256) / 256, 256>>>(pf, n_pairs, n_atoms);
    envsum_kernel<<<n_atoms / ATOMS_PER_BLK, 320>>>(feat, dist, coord, mu, sigma, ps);
    int mtiles = (n_atoms * 4 + BM64 - 1) / BM64;
    gemm_kernel<<<mtiles, 256, 2 * STG_BYTES>>>(selfb, vecs, out, n_atoms);
}

// round 12
// speedup vs baseline: 1.5432x; 1.3188x over previous
#include <cuda_runtime.h>
#include <cuda_bf16.h>
#include <cstdint>

typedef unsigned long long ull;

#define HARD_CUT 6.5f
#define PI_F 3.14159265358979f

#define KTOT 1728            // 1600 scalar + 80 self + 48 zero pad (27*64)
#define KCH  64
#define NCH  27
#define MPAD 20096           // 314*64
#define ATOMS_PER_BLK 4

// smem stage layout (bytes, per buffer) — BM=64 tiles
#define BM64   64
#define OFF_AH 0
#define OFF_AL 8192
#define OFF_BH 16384
#define OFF_BL 26624
#define STG_BYTES 36864

// ---------------- scratch (static __device__, zero-init => pad rows/cols stay 0) ----
__device__ __align__(16) __nv_bfloat16 g_env_hi[(size_t)MPAD * KTOT];
__device__ __align__(16) __nv_bfloat16 g_env_lo[(size_t)MPAD * KTOT];
__device__ __align__(16) __nv_bfloat16 g_w2h[80 * KTOT];   // B[N=80][K] K-major
__device__ __align__(16) __nv_bfloat16 g_w2l[80 * KTOT];
__device__ int g_seg[5008];                                // segment starts per atom

// ---------------- helpers ----------------
__device__ __forceinline__ int lower_bound_i(const int* __restrict__ arr, int n, int val) {
    int lo = 0, hi = n;
    while (lo < hi) { int mid = (lo + hi) >> 1; if (arr[mid] < val) lo = mid + 1; else hi = mid; }
    return lo;
}
__device__ __forceinline__ uint32_t smem_u32(const void* p) {
    uint32_t a;
    asm("{ .reg .u64 t; cvta.to.shared.u64 t, %1; cvt.u32.u64 %0, t; }" : "=r"(a) : "l"(p));
    return a;
}
__device__ __forceinline__ void ldsm4(unsigned* r, uint32_t addr) {
    asm volatile("ldmatrix.sync.aligned.m8n8.x4.shared.b16 {%0,%1,%2,%3}, [%4];"
        : "=r"(r[0]), "=r"(r[1]), "=r"(r[2]), "=r"(r[3]) : "r"(addr));
}
__device__ __forceinline__ void ldsm2(unsigned* r, uint32_t addr) {
    asm volatile("ldmatrix.sync.aligned.m8n8.x2.shared.b16 {%0,%1}, [%2];"
        : "=r"(r[0]), "=r"(r[1]) : "r"(addr));
}
__device__ __forceinline__ void ldsm4t(unsigned* r, uint32_t addr) {
    asm volatile("ldmatrix.sync.aligned.m8n8.x4.trans.shared.b16 {%0,%1,%2,%3}, [%4];"
        : "=r"(r[0]), "=r"(r[1]), "=r"(r[2]), "=r"(r[3]) : "r"(addr));
}
__device__ __forceinline__ void ldsm2t(unsigned* r, uint32_t addr) {
    asm volatile("ldmatrix.sync.aligned.m8n8.x2.trans.shared.b16 {%0,%1}, [%2];"
        : "=r"(r[0]), "=r"(r[1]) : "r"(addr));
}
__device__ __forceinline__ void mma16816(float* d, const unsigned* a, const unsigned* b) {
    asm volatile("mma.sync.aligned.m16n8k16.row.col.f32.bf16.bf16.f32 "
        "{%0,%1,%2,%3}, {%4,%5,%6,%7}, {%8,%9}, {%0,%1,%2,%3};"
        : "+f"(d[0]), "+f"(d[1]), "+f"(d[2]), "+f"(d[3])
        : "r"(a[0]), "r"(a[1]), "r"(a[2]), "r"(a[3]), "r"(b[0]), "r"(b[1]));
}
#define CP16(dst, src)  asm volatile("cp.async.cg.shared.global [%0], [%1], 16;" :: "r"(dst), "l"(src) : "memory")
#define CP_COMMIT()     asm volatile("cp.async.commit_group;" ::: "memory")
#define CP_WAIT1()      asm volatile("cp.async.wait_group 1;" ::: "memory")
#define CP_WAIT0()      asm volatile("cp.async.wait_group 0;" ::: "memory")

// ---------------- K0a: W2 -> bf16 hi/lo, [80 o][1728 k] K-major ----------------
__global__ void build_w_kernel(const float* __restrict__ iw, const float* __restrict__ selfw) {
    int idx = blockIdx.x * blockDim.x + threadIdx.x;
    if (idx >= 80 * KTOT) return;
    int o = idx / KTOT, k = idx % KTOT;
    float v = 0.0f;
    if (k < 1600)      { int s = k / 80, f = k % 80; v = iw[s * 6400 + o * 80 + f]; }
    else if (k < 1680) { v = selfw[o * 80 + (k - 1600)]; }
    __nv_bfloat16 h = __float2bfloat16(v);
    __nv_bfloat16 l = __float2bfloat16(v - __bfloat162float(h));
    g_w2h[idx] = h;
    g_w2l[idx] = l;
}

// ---------------- K0b: segment boundaries ----------------
__global__ void seg_kernel(const int* __restrict__ pf, int n_pairs, int n_atoms) {
    int a = blockIdx.x * blockDim.x + threadIdx.x;
    if (a <= n_atoms) g_seg[a] = lower_bound_i(pf, n_pairs, a);
}

// ---------------- K1: envsum via mma.sync ----------------
// 4 atoms/block, 320 threads (10 warps). Per-atom chunks of 16 pairs.
// Producer (R8 math): 20 lanes/pair -> coef[16][80] and feat[16][80] as bf16 hi/lo
// (stride 88 -> conflict-free ldsm.trans). Consumer: warp (mw=wid%5, nw=wid/5)
// owns cs rows [mw*16,+16) x f cols [nw*40,+40); 3-pass hi/lo mma into fp32 acc.
#define CF_STRIDE 88

__device__ __forceinline__ void flush_mma(float acc[5][4], int a, int cs0, int f0w, int lane) {
    int r0 = cs0 + (lane >> 2);
    int fb = f0w + (lane & 3) * 2;
    #pragma unroll
    for (int nt = 0; nt < 5; nt++) {
        int f = fb + nt * 8;
        #pragma unroll
        for (int h = 0; h < 2; h++) {
            int row = r0 + h * 8;
            float v0 = acc[nt][2 * h], v1 = acc[nt][2 * h + 1];
            int c = row / 20, s = row % 20;
            size_t idx = (size_t)(a * 4 + c) * KTOT + s * 80 + f;
            __nv_bfloat16 h0 = __float2bfloat16(v0);
            __nv_bfloat16 l0 = __float2bfloat16(v0 - __bfloat162float(h0));
            __nv_bfloat16 h1 = __float2bfloat16(v1);
            __nv_bfloat16 l1 = __float2bfloat16(v1 - __bfloat162float(h1));
            __nv_bfloat162 hh; hh.x = h0; hh.y = h1;
            __nv_bfloat162 ll; ll.x = l0; ll.y = l1;
            *(__nv_bfloat162*)&g_env_hi[idx] = hh;
            *(__nv_bfloat162*)&g_env_lo[idx] = ll;
            acc[nt][2 * h] = 0.0f;
            acc[nt][2 * h + 1] = 0.0f;
        }
    }
}

__global__ __launch_bounds__(320) void envsum_kernel(
    const float* __restrict__ feat, const float* __restrict__ dist,
    const float* __restrict__ coord, const float* __restrict__ mu,
    const float* __restrict__ sigma, const int* __restrict__ ps)
{
    __shared__ __align__(16) __nv_bfloat16 s_cfH[16 * CF_STRIDE];
    __shared__ __align__(16) __nv_bfloat16 s_cfL[16 * CF_STRIDE];
    __shared__ __align__(16) __nv_bfloat16 s_ftH[16 * CF_STRIDE];
    __shared__ __align__(16) __nv_bfloat16 s_ftL[16 * CF_STRIDE];

    int a0  = blockIdx.x * ATOMS_PER_BLK;
    int tid = threadIdx.x;
    int lane = tid & 31, wid = tid >> 5;

    int segs[ATOMS_PER_BLK + 1];
    #pragma unroll
    for (int i = 0; i <= ATOMS_PER_BLK; i++) segs[i] = g_seg[a0 + i];
    int cum[ATOMS_PER_BLK + 1];
    cum[0] = 0;
    #pragma unroll
    for (int i = 0; i < ATOMS_PER_BLK; i++)
        cum[i + 1] = cum[i] + ((segs[i + 1] - segs[i] + 15) >> 4);
    int T = cum[ATOMS_PER_BLK];

    // consumer roles
    int mw = wid % 5, nw = wid / 5;
    int cs0 = mw * 16, f0w = nw * 40;
    uint32_t uCfH = smem_u32(s_cfH), uCfL = smem_u32(s_cfL);
    uint32_t uFtH = smem_u32(s_ftH), uFtL = smem_u32(s_ftL);
    int krowA = (lane & 7) + ((lane >> 4) & 1) * 8;
    int krowB = (lane & 7) + ((lane >> 3) & 1) * 8;
    uint32_t aoff  = (uint32_t)(krowA * (CF_STRIDE * 2) + (cs0 + ((lane >> 3) & 1) * 8) * 2);
    uint32_t boff0 = (uint32_t)(krowB * (CF_STRIDE * 2) + (f0w + ((lane >> 4) & 1) * 8) * 2);
    uint32_t boff1 = boff0 + 32;
    uint32_t boff2 = (uint32_t)(krowB * (CF_STRIDE * 2) + (f0w + 32) * 2);

    float acc[5][4];
    #pragma unroll
    for (int nt = 0; nt < 5; nt++)
        #pragma unroll
        for (int q = 0; q < 4; q++) acc[nt][q] = 0.0f;

    // producer roles
    int pp = tid / 20;
    int j  = tid - pp * 20;
    float muj = mu[j];
    float isj = 1.0f / sigma[j];

    // prefetch chunk 0
    float nd = 1.0f, nx = 0.f, ny = 0.f, nz = 0.f;
    float4 nf = make_float4(0.f, 0.f, 0.f, 0.f);
    int have = 0;
    if (T > 0) {
        int at = 0;
        while (at < ATOMS_PER_BLK - 1 && 0 >= cum[at + 1]) at++;
        int p = segs[at] + pp;
        if (p < segs[at + 1]) {
            nd = dist[p]; nx = coord[3 * p]; ny = coord[3 * p + 1]; nz = coord[3 * p + 2];
            int r = ps[p]; nf = ((const float4*)feat)[r * 20 + j];
            have = 1;
        }
    }

    int cur_at = 0;
    for (int t = 0; t < T; t++) {
        while (cur_at < ATOMS_PER_BLK - 1 && t >= cum[cur_at + 1]) cur_at++;
        __syncthreads();                    // consumers done with smem

        // produce chunk t (always write; zeros on padding lanes)
        {
            float c0 = 0.f, c1 = 0.f, c2 = 0.f, c3 = 0.f;
            float4 fv = make_float4(0.f, 0.f, 0.f, 0.f);
            if (have) {
                float inv = 1.0f / nd;
                float cut = (nd < HARD_CUT) ? 0.5f * (__cosf(PI_F * nd * (1.0f / HARD_CUT)) + 1.0f) : 0.0f;
                float z   = (inv - muj) * isj;
                float e   = __expf(-0.5f * z * z) * cut;
                c0 = e; c1 = e * nx * inv; c2 = e * ny * inv; c3 = e * nz * inv;
                fv = nf;
            }
            int cb = pp * CF_STRIDE + j;
            float cv[4] = {c0, c1, c2, c3};
            #pragma unroll
            for (int cc = 0; cc < 4; cc++) {
                __nv_bfloat16 h = __float2bfloat16(cv[cc]);
                __nv_bfloat16 l = __float2bfloat16(cv[cc] - __bfloat162float(h));
                s_cfH[cb + cc * 20] = h;
                s_cfL[cb + cc * 20] = l;
            }
            __nv_bfloat16 fh[4], fl[4];
            float fa[4] = {fv.x, fv.y, fv.z, fv.w};
            #pragma unroll
            for (int q = 0; q < 4; q++) {
                fh[q] = __float2bfloat16(fa[q]);
                fl[q] = __float2bfloat16(fa[q] - __bfloat162float(fh[q]));
            }
            int fb = pp * CF_STRIDE + j * 4;
            __nv_bfloat162 p0; p0.x = fh[0]; p0.y = fh[1];
            __nv_bfloat162 p1; p1.x = fh[2]; p1.y = fh[3];
            __nv_bfloat162 q0; q0.x = fl[0]; q0.y = fl[1];
            __nv_bfloat162 q1; q1.x = fl[2]; q1.y = fl[3];
            *(__nv_bfloat162*)&s_ftH[fb]     = p0;
            *(__nv_bfloat162*)&s_ftH[fb + 2] = p1;
            *(__nv_bfloat162*)&s_ftL[fb]     = q0;
            *(__nv_bfloat162*)&s_ftL[fb + 2] = q1;
        }
        __syncthreads();                    // tiles ready

        // prefetch chunk t+1 (overlaps consume)
        have = 0;
        nf = make_float4(0.f, 0.f, 0.f, 0.f);
        if (t + 1 < T) {
            int at2 = cur_at;
            while (at2 < ATOMS_PER_BLK - 1 && t + 1 >= cum[at2 + 1]) at2++;
            int p = segs[at2] + (t + 1 - cum[at2]) * 16 + pp;
            if (p < segs[at2 + 1]) {
                nd = dist[p]; nx = coord[3 * p]; ny = coord[3 * p + 1]; nz = coord[3 * p + 2];
                int r = ps[p]; nf = ((const float4*)feat)[r * 20 + j];
                have = 1;
            }
        }

        // consume: ldsm.trans + 15 mma
        {
            unsigned aH[4], aL[4], bH[10], bL[10];
            ldsm4t(aH, uCfH + aoff);
            ldsm4t(aL, uCfL + aoff);
            ldsm4t(bH + 0, uFtH + boff0);
            ldsm4t(bH + 4, uFtH + boff1);
            ldsm2t(bH + 8, uFtH + boff2);
            ldsm4t(bL + 0, uFtL + boff0);
            ldsm4t(bL + 4, uFtL + boff1);
            ldsm2t(bL + 8, uFtL + boff2);
            #pragma unroll
            for (int nt = 0; nt < 5; nt++) {
                mma16816(acc[nt], aH, bH + 2 * nt);
                mma16816(acc[nt], aL, bH + 2 * nt);
                mma16816(acc[nt], aH, bL + 2 * nt);
            }
        }

        // last chunk of this atom -> flush accumulators
        if (t == cum[cur_at + 1] - 1)
            flush_mma(acc, a0 + cur_at, cs0, f0w, lane);
    }

    // atoms with zero pairs: flush zeros (acc is zero here)
    #pragma unroll
    for (int i = 0; i < ATOMS_PER_BLK; i++)
        if (cum[i + 1] == cum[i])
            flush_mma(acc, a0 + i, cs0, f0w, lane);

    // self-interaction rows: env[(a,c), 1600+f] = (c==0) ? feat[a,f] : 0
    {
        int c2 = tid / 80;   // 0..3
        int f  = tid % 80;
        #pragma unroll
        for (int ai = 0; ai < ATOMS_PER_BLK; ai++) {
            int a = a0 + ai;
            float v = (c2 == 0) ? feat[a * 80 + f] : 0.0f;
            __nv_bfloat16 h = __float2bfloat16(v);
            __nv_bfloat16 l = __float2bfloat16(v - __bfloat162float(h));
            size_t off = (size_t)(a * 4 + c2) * KTOT + 1600 + f;
            g_env_hi[off] = h;
            g_env_lo[off] = l;
        }
    }
}

// ---------------- K2: bf16-split GEMM, BM=64, 2 CTAs/SM (unchanged, known-good) ------
__device__ __forceinline__ void load_stage(uint32_t sstage, int m0, int kc, int tid) {
    #pragma unroll
    for (int i = 0; i < 2; i++) {
        int u = tid + i * 256;                 // 512: 64 rows x 8 segs
        int r = u >> 3, sg = u & 7;
        uint32_t so = (uint32_t)(r * 128 + ((sg ^ (r & 7)) * 16));
        const char* gh = (const char*)(g_env_hi + (size_t)(m0 + r) * KTOT + kc) + sg * 16;
        const char* gl = (const char*)(g_env_lo + (size_t)(m0 + r) * KTOT + kc) + sg * 16;
        CP16(sstage + OFF_AH + so, gh);
        CP16(sstage + OFF_AL + so, gl);
    }
    #pragma unroll
    for (int i = 0; i < 3; i++) {
        int u = tid + i * 256;                 // 640: 80 rows x 8 segs
        if (u < 640) {
            int r = u >> 3, sg = u & 7;
            uint32_t so = (uint32_t)(r * 128 + ((sg ^ (r & 7)) * 16));
            const char* gh = (const char*)(g_w2h + (size_t)r * KTOT + kc) + sg * 16;
            const char* gl = (const char*)(g_w2l + (size_t)r * KTOT + kc) + sg * 16;
            CP16(sstage + OFF_BH + so, gh);
            CP16(sstage + OFF_BL + so, gl);
        }
    }
}

__global__ __launch_bounds__(256, 2)
void gemm_kernel(const float* __restrict__ selfb, const float* __restrict__ vecs,
                 float* __restrict__ out, int n_atoms)
{
    extern __shared__ __align__(1024) char smem[];
    uint32_t sb = smem_u32(smem);
    int tid  = threadIdx.x;
    int lane = tid & 31;
    int wid  = tid >> 5;
    int m0   = blockIdx.x * BM64;
    int m0w  = (wid >> 1) * 16;
    int n0w  = (wid & 1) * 40;

    int rA_loc = (lane & 7) + ((lane >> 3) & 1) * 8;
    uint32_t rowA0 = (uint32_t)((m0w + rA_loc) * 128);
    int rB_loc = (lane & 7) + ((lane >> 4) & 1) * 8;
    uint32_t rowB0 = (uint32_t)((n0w + rB_loc) * 128);
    uint32_t rowB1 = rowB0 + 16 * 128;
    uint32_t rowB2 = (uint32_t)((n0w + 32 + (lane & 7)) * 128);

    float acc[5][4];
    #pragma unroll
    for (int nt = 0; nt < 5; nt++)
        #pragma unroll
        for (int q = 0; q < 4; q++) acc[nt][q] = 0.0f;

    load_stage(sb, m0, 0, tid);               CP_COMMIT();
    load_stage(sb + STG_BYTES, m0, KCH, tid); CP_COMMIT();

    for (int c = 0; c < NCH; c++) {
        if (c < NCH - 1) CP_WAIT1(); else CP_WAIT0();
        __syncthreads();

        uint32_t st  = sb + (uint32_t)((c & 1) * STG_BYTES);
        uint32_t sAH = st + OFF_AH, sAL = st + OFF_AL;
        uint32_t sBH = st + OFF_BH, sBL = st + OFF_BL;

        #pragma unroll
        for (int ks = 0; ks < 4; ks++) {
            uint32_t swA = (uint32_t)((((ks * 2) + (lane >> 4)) ^ (lane & 7)) * 16);
            uint32_t swB = (uint32_t)((((ks * 2) + ((lane >> 3) & 1)) ^ (lane & 7)) * 16);
            unsigned aH[4], aL[4], bH[10], bL[10];
            ldsm4(aH, sAH + rowA0 + swA);
            ldsm4(aL, sAL + rowA0 + swA);
            ldsm4(bH + 0, sBH + rowB0 + swB);
            ldsm4(bH + 4, sBH + rowB1 + swB);
            ldsm2(bH + 8, sBH + rowB2 + swB);
            ldsm4(bL + 0, sBL + rowB0 + swB);
            ldsm4(bL + 4, sBL + rowB1 + swB);
            ldsm2(bL + 8, sBL + rowB2 + swB);
            #pragma unroll
            for (int nt = 0; nt < 5; nt++) {
                mma16816(acc[nt], aH, bH + 2 * nt);
                mma16816(acc[nt], aL, bH + 2 * nt);
                mma16816(acc[nt], aH, bL + 2 * nt);
            }
        }
        __syncthreads();
        if (c + 2 < NCH) { load_stage(sb + (uint32_t)((c & 1) * STG_BYTES), m0, (c + 2) * KCH, tid); CP_COMMIT(); }
    }

    // write accumulators to smem C[64][80]
    float* C = (float*)smem;
    int grp  = lane >> 2;
    int col0 = (lane & 3) * 2;
    {
        int r0 = m0w + grp;
        #pragma unroll
        for (int nt = 0; nt < 5; nt++) {
            int cc = n0w + nt * 8 + col0;
            *(float2*)&C[r0 * 80 + cc]       = make_float2(acc[nt][0], acc[nt][1]);
            *(float2*)&C[(r0 + 8) * 80 + cc] = make_float2(acc[nt][2], acc[nt][3]);
        }
    }
    __syncthreads();

    #pragma unroll
    for (int u = tid; u < 1280; u += 256) {
        int al = u / 80, o = u % 80;
        int a = (m0 >> 2) + al;
        if (a < n_atoms) {
            float s0 = C[(al * 4 + 0) * 80 + o];
            float x  = C[(al * 4 + 1) * 80 + o];
            float y  = C[(al * 4 + 2) * 80 + o];
            float z  = C[(al * 4 + 3) * 80 + o];
            out[a * 80 + o] = s0 + selfb[o]
                + vecs[o] * sqrtf(fmaf(x, x, fmaf(y, y, z * z)) + 1e-30f);
        }
    }
}

// ---------------- launch ----------------
extern "C" void kernel_launch(void* const* d_in, const int* in_sizes, int n_in,
                              void* d_out, int out_size) {
    const float* feat  = (const float*)d_in[0];
    const float* dist  = (const float*)d_in[1];
    const float* coord = (const float*)d_in[2];
    const float* iw    = (const float*)d_in[3];
    const float* selfw = (const float*)d_in[4];
    const float* selfb = (const float*)d_in[5];
    const float* vecs  = (const float*)d_in[6];
    const float* mu    = (const float*)d_in[7];
    const float* sigma = (const float*)d_in[8];
    const int*   pf    = (const int*)d_in[9];
    const int*   ps    = (const int*)d_in[10];
    int n_pairs = in_sizes[9];
    int n_atoms = in_sizes[0] / 80;
    float* out = (float*)d_out;

    static int smem_set = 0;
    if (!smem_set) {
        cudaFuncSetAttribute(gemm_kernel, cudaFuncAttributeMaxDynamicSharedMemorySize,
                             2 * STG_BYTES);
        smem_set = 1;
    }

    build_w_kernel<<<(80 * KTOT + 255) / 256, 256>>>(iw, selfw);
    seg_kernel<<<(n_atoms + 256) / 256, 256>>>(pf, n_pairs, n_atoms);
    envsum_kernel<<<n_atoms / ATOMS_PER_BLK, 320>>>(feat, dist, coord, mu, sigma, ps);
    int mtiles = (n_atoms * 4 + BM64 - 1) / BM64;
    gemm_kernel<<<mtiles, 256, 2 * STG_BYTES>>>(selfb, vecs, out, n_atoms);
}

// round 13
// speedup vs baseline: 1.5564x; 1.0085x over previous
#include <cuda_runtime.h>
#include <cuda_bf16.h>
#include <cstdint>

typedef unsigned long long ull;

#define HARD_CUT 6.5f
#define PI_F 3.14159265358979f

#define KTOT 1728            // 1600 scalar + 80 self + 48 zero pad (27*64)
#define KCH  64
#define NCH  27
#define MPAD 20096           // 314*64
#define ATOMS_PER_BLK 4

// smem stage layout (bytes, per buffer) — BM=64 tiles
#define BM64   64
#define OFF_AH 0
#define OFF_AL 8192
#define OFF_BH 16384
#define OFF_BL 26624
#define STG_BYTES 36864

// ---------------- scratch (static __device__, zero-init => pad rows/cols stay 0) ----
__device__ __align__(16) __nv_bfloat16 g_env_hi[(size_t)MPAD * KTOT];
__device__ __align__(16) __nv_bfloat16 g_env_lo[(size_t)MPAD * KTOT];
__device__ __align__(16) __nv_bfloat16 g_w2h[80 * KTOT];   // B[N=80][K] K-major
__device__ __align__(16) __nv_bfloat16 g_w2l[80 * KTOT];
__device__ int g_seg[5008];                                // segment starts per atom

// ---------------- helpers ----------------
__device__ __forceinline__ int lower_bound_i(const int* __restrict__ arr, int n, int val) {
    int lo = 0, hi = n;
    while (lo < hi) { int mid = (lo + hi) >> 1; if (arr[mid] < val) lo = mid + 1; else hi = mid; }
    return lo;
}
__device__ __forceinline__ uint32_t smem_u32(const void* p) {
    uint32_t a;
    asm("{ .reg .u64 t; cvta.to.shared.u64 t, %1; cvt.u32.u64 %0, t; }" : "=r"(a) : "l"(p));
    return a;
}
__device__ __forceinline__ void ldsm4(unsigned* r, uint32_t addr) {
    asm volatile("ldmatrix.sync.aligned.m8n8.x4.shared.b16 {%0,%1,%2,%3}, [%4];"
        : "=r"(r[0]), "=r"(r[1]), "=r"(r[2]), "=r"(r[3]) : "r"(addr));
}
__device__ __forceinline__ void ldsm2(unsigned* r, uint32_t addr) {
    asm volatile("ldmatrix.sync.aligned.m8n8.x2.shared.b16 {%0,%1}, [%2];"
        : "=r"(r[0]), "=r"(r[1]) : "r"(addr));
}
__device__ __forceinline__ void ldsm4t(unsigned* r, uint32_t addr) {
    asm volatile("ldmatrix.sync.aligned.m8n8.x4.trans.shared.b16 {%0,%1,%2,%3}, [%4];"
        : "=r"(r[0]), "=r"(r[1]), "=r"(r[2]), "=r"(r[3]) : "r"(addr));
}
__device__ __forceinline__ void ldsm2t(unsigned* r, uint32_t addr) {
    asm volatile("ldmatrix.sync.aligned.m8n8.x2.trans.shared.b16 {%0,%1}, [%2];"
        : "=r"(r[0]), "=r"(r[1]) : "r"(addr));
}
__device__ __forceinline__ void mma16816(float* d, const unsigned* a, const unsigned* b) {
    asm volatile("mma.sync.aligned.m16n8k16.row.col.f32.bf16.bf16.f32 "
        "{%0,%1,%2,%3}, {%4,%5,%6,%7}, {%8,%9}, {%0,%1,%2,%3};"
        : "+f"(d[0]), "+f"(d[1]), "+f"(d[2]), "+f"(d[3])
        : "r"(a[0]), "r"(a[1]), "r"(a[2]), "r"(a[3]), "r"(b[0]), "r"(b[1]));
}
#define CP16(dst, src)  asm volatile("cp.async.cg.shared.global [%0], [%1], 16;" :: "r"(dst), "l"(src) : "memory")
#define CP_COMMIT()     asm volatile("cp.async.commit_group;" ::: "memory")
#define CP_WAIT1()      asm volatile("cp.async.wait_group 1;" ::: "memory")
#define CP_WAIT0()      asm volatile("cp.async.wait_group 0;" ::: "memory")

// ---------------- K0a: W2 -> bf16 hi/lo, [80 o][1728 k] K-major ----------------
__global__ void build_w_kernel(const float* __restrict__ iw, const float* __restrict__ selfw) {
    int idx = blockIdx.x * blockDim.x + threadIdx.x;
    if (idx >= 80 * KTOT) return;
    int o = idx / KTOT, k = idx % KTOT;
    float v = 0.0f;
    if (k < 1600)      { int s = k / 80, f = k % 80; v = iw[s * 6400 + o * 80 + f]; }
    else if (k < 1680) { v = selfw[o * 80 + (k - 1600)]; }
    __nv_bfloat16 h = __float2bfloat16(v);
    __nv_bfloat16 l = __float2bfloat16(v - __bfloat162float(h));
    g_w2h[idx] = h;
    g_w2l[idx] = l;
}

// ---------------- K0b: segment boundaries ----------------
__global__ void seg_kernel(const int* __restrict__ pf, int n_pairs, int n_atoms) {
    int a = blockIdx.x * blockDim.x + threadIdx.x;
    if (a <= n_atoms) g_seg[a] = lower_bound_i(pf, n_pairs, a);
}

// ---------------- K1: envsum via mma.sync, double-buffered tiles ----------------
// 4 atoms/block, 320 threads (10 warps). Per-atom chunks of 16 pairs.
// Producer: 20 lanes/pair -> coef[16][80], feat[16][80] bf16 hi/lo (stride 88).
// Double-buffered smem tiles -> ONE barrier per chunk.
// Consumer: warp (mw=wid%5, nw=wid/5) owns cs [mw*16,+16) x f [nw*40,+40).
#define CF_STRIDE 88
#define CF_ELEMS  (16 * CF_STRIDE)
#define CF_BYTES  (CF_ELEMS * 2)

__device__ __forceinline__ void flush_mma(float acc[5][4], int a, int cs0, int f0w, int lane) {
    int r0 = cs0 + (lane >> 2);
    int fb = f0w + (lane & 3) * 2;
    #pragma unroll
    for (int nt = 0; nt < 5; nt++) {
        int f = fb + nt * 8;
        #pragma unroll
        for (int h = 0; h < 2; h++) {
            int row = r0 + h * 8;
            float v0 = acc[nt][2 * h], v1 = acc[nt][2 * h + 1];
            int c = row / 20, s = row % 20;
            size_t idx = (size_t)(a * 4 + c) * KTOT + s * 80 + f;
            __nv_bfloat16 h0 = __float2bfloat16(v0);
            __nv_bfloat16 l0 = __float2bfloat16(v0 - __bfloat162float(h0));
            __nv_bfloat16 h1 = __float2bfloat16(v1);
            __nv_bfloat16 l1 = __float2bfloat16(v1 - __bfloat162float(h1));
            __nv_bfloat162 hh; hh.x = h0; hh.y = h1;
            __nv_bfloat162 ll; ll.x = l0; ll.y = l1;
            *(__nv_bfloat162*)&g_env_hi[idx] = hh;
            *(__nv_bfloat162*)&g_env_lo[idx] = ll;
            acc[nt][2 * h] = 0.0f;
            acc[nt][2 * h + 1] = 0.0f;
        }
    }
}

__global__ __launch_bounds__(320) void envsum_kernel(
    const float* __restrict__ feat, const float* __restrict__ dist,
    const float* __restrict__ coord, const float* __restrict__ mu,
    const float* __restrict__ sigma, const int* __restrict__ ps)
{
    __shared__ __align__(16) __nv_bfloat16 s_cfH[2 * CF_ELEMS];
    __shared__ __align__(16) __nv_bfloat16 s_cfL[2 * CF_ELEMS];
    __shared__ __align__(16) __nv_bfloat16 s_ftH[2 * CF_ELEMS];
    __shared__ __align__(16) __nv_bfloat16 s_ftL[2 * CF_ELEMS];

    int a0  = blockIdx.x * ATOMS_PER_BLK;
    int tid = threadIdx.x;
    int lane = tid & 31, wid = tid >> 5;

    int segs[ATOMS_PER_BLK + 1];
    #pragma unroll
    for (int i = 0; i <= ATOMS_PER_BLK; i++) segs[i] = g_seg[a0 + i];
    int cum[ATOMS_PER_BLK + 1];
    cum[0] = 0;
    #pragma unroll
    for (int i = 0; i < ATOMS_PER_BLK; i++)
        cum[i + 1] = cum[i] + ((segs[i + 1] - segs[i] + 15) >> 4);
    int T = cum[ATOMS_PER_BLK];

    // consumer roles
    int mw = wid % 5, nw = wid / 5;
    int cs0 = mw * 16, f0w = nw * 40;
    uint32_t uCfH = smem_u32(s_cfH), uCfL = smem_u32(s_cfL);
    uint32_t uFtH = smem_u32(s_ftH), uFtL = smem_u32(s_ftL);
    int krowA = (lane & 7) + ((lane >> 4) & 1) * 8;
    int krowB = (lane & 7) + ((lane >> 3) & 1) * 8;
    uint32_t aoff  = (uint32_t)(krowA * (CF_STRIDE * 2) + (cs0 + ((lane >> 3) & 1) * 8) * 2);
    uint32_t boff0 = (uint32_t)(krowB * (CF_STRIDE * 2) + (f0w + ((lane >> 4) & 1) * 8) * 2);
    uint32_t boff1 = boff0 + 32;
    uint32_t boff2 = (uint32_t)(krowB * (CF_STRIDE * 2) + (f0w + 32) * 2);

    float acc[5][4];
    #pragma unroll
    for (int nt = 0; nt < 5; nt++)
        #pragma unroll
        for (int q = 0; q < 4; q++) acc[nt][q] = 0.0f;

    // producer roles
    int pp = tid / 20;
    int j  = tid - pp * 20;
    float muj = mu[j];
    float isj = 1.0f / sigma[j];

    // prefetch chunk 0
    float nd = 1.0f, nx = 0.f, ny = 0.f, nz = 0.f;
    float4 nf = make_float4(0.f, 0.f, 0.f, 0.f);
    int have = 0;
    if (T > 0) {
        int at = 0;
        while (at < ATOMS_PER_BLK - 1 && 0 >= cum[at + 1]) at++;
        int p = segs[at] + pp;
        if (p < segs[at + 1]) {
            nd = dist[p]; nx = coord[3 * p]; ny = coord[3 * p + 1]; nz = coord[3 * p + 2];
            int r = ps[p]; nf = ((const float4*)feat)[r * 20 + j];
            have = 1;
        }
    }

    int cur_at = 0;
    for (int t = 0; t < T; t++) {
        while (cur_at < ATOMS_PER_BLK - 1 && t >= cum[cur_at + 1]) cur_at++;
        int bsel = t & 1;
        uint32_t bofs = (uint32_t)(bsel * CF_BYTES);
        __nv_bfloat16* cfH = s_cfH + bsel * CF_ELEMS;
        __nv_bfloat16* cfL = s_cfL + bsel * CF_ELEMS;
        __nv_bfloat16* ftH = s_ftH + bsel * CF_ELEMS;
        __nv_bfloat16* ftL = s_ftL + bsel * CF_ELEMS;

        // produce chunk t into buffer bsel (last read at t-2; sync at t-1 separates)
        {
            float c0 = 0.f, c1 = 0.f, c2 = 0.f, c3 = 0.f;
            float4 fv = make_float4(0.f, 0.f, 0.f, 0.f);
            if (have) {
                float inv = 1.0f / nd;
                float cut = (nd < HARD_CUT) ? 0.5f * (__cosf(PI_F * nd * (1.0f / HARD_CUT)) + 1.0f) : 0.0f;
                float z   = (inv - muj) * isj;
                float e   = __expf(-0.5f * z * z) * cut;
                c0 = e; c1 = e * nx * inv; c2 = e * ny * inv; c3 = e * nz * inv;
                fv = nf;
            }
            int cb = pp * CF_STRIDE + j;
            float cv[4] = {c0, c1, c2, c3};
            #pragma unroll
            for (int cc = 0; cc < 4; cc++) {
                __nv_bfloat16 h = __float2bfloat16(cv[cc]);
                __nv_bfloat16 l = __float2bfloat16(cv[cc] - __bfloat162float(h));
                cfH[cb + cc * 20] = h;
                cfL[cb + cc * 20] = l;
            }
            __nv_bfloat16 fh[4], fl[4];
            float fa[4] = {fv.x, fv.y, fv.z, fv.w};
            #pragma unroll
            for (int q = 0; q < 4; q++) {
                fh[q] = __float2bfloat16(fa[q]);
                fl[q] = __float2bfloat16(fa[q] - __bfloat162float(fh[q]));
            }
            int fb = pp * CF_STRIDE + j * 4;
            __nv_bfloat162 p0; p0.x = fh[0]; p0.y = fh[1];
            __nv_bfloat162 p1; p1.x = fh[2]; p1.y = fh[3];
            __nv_bfloat162 q0; q0.x = fl[0]; q0.y = fl[1];
            __nv_bfloat162 q1; q1.x = fl[2]; q1.y = fl[3];
            *(__nv_bfloat162*)&ftH[fb]     = p0;
            *(__nv_bfloat162*)&ftH[fb + 2] = p1;
            *(__nv_bfloat162*)&ftL[fb]     = q0;
            *(__nv_bfloat162*)&ftL[fb + 2] = q1;
        }
        __syncthreads();                    // tiles ready (single barrier per chunk)

        // prefetch chunk t+1 (overlaps consume)
        have = 0;
        nf = make_float4(0.f, 0.f, 0.f, 0.f);
        if (t + 1 < T) {
            int at2 = cur_at;
            while (at2 < ATOMS_PER_BLK - 1 && t + 1 >= cum[at2 + 1]) at2++;
            int p = segs[at2] + (t + 1 - cum[at2]) * 16 + pp;
            if (p < segs[at2 + 1]) {
                nd = dist[p]; nx = coord[3 * p]; ny = coord[3 * p + 1]; nz = coord[3 * p + 2];
                int r = ps[p]; nf = ((const float4*)feat)[r * 20 + j];
                have = 1;
            }
        }

        // consume: ldsm.trans + 15 mma
        {
            unsigned aH[4], aL[4], bH[10], bL[10];
            ldsm4t(aH, uCfH + bofs + aoff);
            ldsm4t(aL, uCfL + bofs + aoff);
            ldsm4t(bH + 0, uFtH + bofs + boff0);
            ldsm4t(bH + 4, uFtH + bofs + boff1);
            ldsm2t(bH + 8, uFtH + bofs + boff2);
            ldsm4t(bL + 0, uFtL + bofs + boff0);
            ldsm4t(bL + 4, uFtL + bofs + boff1);
            ldsm2t(bL + 8, uFtL + bofs + boff2);
            #pragma unroll
            for (int nt = 0; nt < 5; nt++) {
                mma16816(acc[nt], aH, bH + 2 * nt);
                mma16816(acc[nt], aL, bH + 2 * nt);
                mma16816(acc[nt], aH, bL + 2 * nt);
            }
        }

        if (t == cum[cur_at + 1] - 1)
            flush_mma(acc, a0 + cur_at, cs0, f0w, lane);
    }

    #pragma unroll
    for (int i = 0; i < ATOMS_PER_BLK; i++)
        if (cum[i + 1] == cum[i])
            flush_mma(acc, a0 + i, cs0, f0w, lane);

    // self-interaction rows: env[(a,c), 1600+f] = (c==0) ? feat[a,f] : 0
    {
        int c2 = tid / 80;   // 0..3
        int f  = tid % 80;
        #pragma unroll
        for (int ai = 0; ai < ATOMS_PER_BLK; ai++) {
            int a = a0 + ai;
            float v = (c2 == 0) ? feat[a * 80 + f] : 0.0f;
            __nv_bfloat16 h = __float2bfloat16(v);
            __nv_bfloat16 l = __float2bfloat16(v - __bfloat162float(h));
            size_t off = (size_t)(a * 4 + c2) * KTOT + 1600 + f;
            g_env_hi[off] = h;
            g_env_lo[off] = l;
        }
    }
}

// ---------------- K2: bf16-split GEMM, BM=64, m32n40 warp tiles + 2-way k-split ----
// 8 warps: wg = wid>>2 owns ks {wg*2, wg*2+1}; wi = wid&3 -> (mw=wi>>1)*32 m-rows,
// (nw=wi&1)*40 n-cols. Partials merged through the C smem tile at the end.
__device__ __forceinline__ void load_stage(uint32_t sstage, int m0, int kc, int tid) {
    #pragma unroll
    for (int i = 0; i < 2; i++) {
        int u = tid + i * 256;                 // 512: 64 rows x 8 segs
        int r = u >> 3, sg = u & 7;
        uint32_t so = (uint32_t)(r * 128 + ((sg ^ (r & 7)) * 16));
        const char* gh = (const char*)(g_env_hi + (size_t)(m0 + r) * KTOT + kc) + sg * 16;
        const char* gl = (const char*)(g_env_lo + (size_t)(m0 + r) * KTOT + kc) + sg * 16;
        CP16(sstage + OFF_AH + so, gh);
        CP16(sstage + OFF_AL + so, gl);
    }
    #pragma unroll
    for (int i = 0; i < 3; i++) {
        int u = tid + i * 256;                 // 640: 80 rows x 8 segs
        if (u < 640) {
            int r = u >> 3, sg = u & 7;
            uint32_t so = (uint32_t)(r * 128 + ((sg ^ (r & 7)) * 16));
            const char* gh = (const char*)(g_w2h + (size_t)r * KTOT + kc) + sg * 16;
            const char* gl = (const char*)(g_w2l + (size_t)r * KTOT + kc) + sg * 16;
            CP16(sstage + OFF_BH + so, gh);
            CP16(sstage + OFF_BL + so, gl);
        }
    }
}

__global__ __launch_bounds__(256, 2)
void gemm_kernel(const float* __restrict__ selfb, const float* __restrict__ vecs,
                 float* __restrict__ out, int n_atoms)
{
    extern __shared__ __align__(1024) char smem[];
    uint32_t sb = smem_u32(smem);
    int tid  = threadIdx.x;
    int lane = tid & 31;
    int wid  = tid >> 5;
    int m0   = blockIdx.x * BM64;

    int wg = wid >> 2;            // k-group: ks in {2*wg, 2*wg+1}
    int wi = wid & 3;
    int m0w = (wi >> 1) * 32;
    int n0w = (wi & 1) * 40;
    int ksBase = wg * 2;

    int rA_loc = (lane & 7) + ((lane >> 3) & 1) * 8;
    uint32_t rowA0 = (uint32_t)((m0w + rA_loc) * 128);
    uint32_t rowA1 = rowA0 + 16 * 128;
    int rB_loc = (lane & 7) + ((lane >> 4) & 1) * 8;
    uint32_t rowB0 = (uint32_t)((n0w + rB_loc) * 128);
    uint32_t rowB1 = rowB0 + 16 * 128;
    uint32_t rowB2 = (uint32_t)((n0w + 32 + (lane & 7)) * 128);

    float acc[2][5][4];
    #pragma unroll
    for (int mt = 0; mt < 2; mt++)
        #pragma unroll
        for (int nt = 0; nt < 5; nt++)
            #pragma unroll
            for (int q = 0; q < 4; q++) acc[mt][nt][q] = 0.0f;

    load_stage(sb, m0, 0, tid);               CP_COMMIT();
    load_stage(sb + STG_BYTES, m0, KCH, tid); CP_COMMIT();

    for (int c = 0; c < NCH; c++) {
        if (c < NCH - 1) CP_WAIT1(); else CP_WAIT0();
        __syncthreads();

        uint32_t st  = sb + (uint32_t)((c & 1) * STG_BYTES);
        uint32_t sAH = st + OFF_AH, sAL = st + OFF_AL;
        uint32_t sBH = st + OFF_BH, sBL = st + OFF_BL;

        #pragma unroll
        for (int kss = 0; kss < 2; kss++) {
            int ks = ksBase + kss;
            uint32_t swA = (uint32_t)((((ks * 2) + (lane >> 4)) ^ (lane & 7)) * 16);
            uint32_t swB = (uint32_t)((((ks * 2) + ((lane >> 3) & 1)) ^ (lane & 7)) * 16);
            unsigned aH[2][4], aL[2][4], bH[10], bL[10];
            ldsm4(aH[0], sAH + rowA0 + swA);
            ldsm4(aH[1], sAH + rowA1 + swA);
            ldsm4(aL[0], sAL + rowA0 + swA);
            ldsm4(aL[1], sAL + rowA1 + swA);
            ldsm4(bH + 0, sBH + rowB0 + swB);
            ldsm4(bH + 4, sBH + rowB1 + swB);
            ldsm2(bH + 8, sBH + rowB2 + swB);
            ldsm4(bL + 0, sBL + rowB0 + swB);
            ldsm4(bL + 4, sBL + rowB1 + swB);
            ldsm2(bL + 8, sBL + rowB2 + swB);
            #pragma unroll
            for (int mt = 0; mt < 2; mt++)
                #pragma unroll
                for (int nt = 0; nt < 5; nt++) {
                    mma16816(acc[mt][nt], aH[mt], bH + 2 * nt);
                    mma16816(acc[mt][nt], aL[mt], bH + 2 * nt);
                    mma16816(acc[mt][nt], aH[mt], bL + 2 * nt);
                }
        }
        __syncthreads();
        if (c + 2 < NCH) { load_stage(sb + (uint32_t)((c & 1) * STG_BYTES), m0, (c + 2) * KCH, tid); CP_COMMIT(); }
    }

    // merge k-split partials through C[64][80] in smem
    float* C = (float*)smem;
    int grp  = lane >> 2;
    int col0 = (lane & 3) * 2;
    if (wg == 1) {
        #pragma unroll
        for (int mt = 0; mt < 2; mt++) {
            int r0 = m0w + mt * 16 + grp;
            #pragma unroll
            for (int nt = 0; nt < 5; nt++) {
                int cc = n0w + nt * 8 + col0;
                *(float2*)&C[r0 * 80 + cc]       = make_float2(acc[mt][nt][0], acc[mt][nt][1]);
                *(float2*)&C[(r0 + 8) * 80 + cc] = make_float2(acc[mt][nt][2], acc[mt][nt][3]);
            }
        }
    }
    __syncthreads();
    if (wg == 0) {
        #pragma unroll
        for (int mt = 0; mt < 2; mt++) {
            int r0 = m0w + mt * 16 + grp;
            #pragma unroll
            for (int nt = 0; nt < 5; nt++) {
                int cc = n0w + nt * 8 + col0;
                float2 v0 = *(float2*)&C[r0 * 80 + cc];
                float2 v1 = *(float2*)&C[(r0 + 8) * 80 + cc];
                v0.x += acc[mt][nt][0]; v0.y += acc[mt][nt][1];
                v1.x += acc[mt][nt][2]; v1.y += acc[mt][nt][3];
                *(float2*)&C[r0 * 80 + cc]       = v0;
                *(float2*)&C[(r0 + 8) * 80 + cc] = v1;
            }
        }
    }
    __syncthreads();

    #pragma unroll
    for (int u = tid; u < 1280; u += 256) {
        int al = u / 80, o = u % 80;
        int a = (m0 >> 2) + al;
        if (a < n_atoms) {
            float s0 = C[(al * 4 + 0) * 80 + o];
            float x  = C[(al * 4 + 1) * 80 + o];
            float y  = C[(al * 4 + 2) * 80 + o];
            float z  = C[(al * 4 + 3) * 80 + o];
            out[a * 80 + o] = s0 + selfb[o]
                + vecs[o] * sqrtf(fmaf(x, x, fmaf(y, y, z * z)) + 1e-30f);
        }
    }
}

// ---------------- launch ----------------
extern "C" void kernel_launch(void* const* d_in, const int* in_sizes, int n_in,
                              void* d_out, int out_size) {
    const float* feat  = (const float*)d_in[0];
    const float* dist  = (const float*)d_in[1];
    const float* coord = (const float*)d_in[2];
    const float* iw    = (const float*)d_in[3];
    const float* selfw = (const float*)d_in[4];
    const float* selfb = (const float*)d_in[5];
    const float* vecs  = (const float*)d_in[6];
    const float* mu    = (const float*)d_in[7];
    const float* sigma = (const float*)d_in[8];
    const int*   pf    = (const int*)d_in[9];
    const int*   ps    = (const int*)d_in[10];
    int n_pairs = in_sizes[9];
    int n_atoms = in_sizes[0] / 80;
    float* out = (float*)d_out;

    static int smem_set = 0;
    if (!smem_set) {
        cudaFuncSetAttribute(gemm_kernel, cudaFuncAttributeMaxDynamicSharedMemorySize,
                             2 * STG_BYTES);
        smem_set = 1;
    }

    build_w_kernel<<<(80 * KTOT + 255) / 256, 256>>>(iw, selfw);
    seg_kernel<<<(n_atoms + 256) / 256, 256>>>(pf, n_pairs, n_atoms);
    envsum_kernel<<<n_atoms / ATOMS_PER_BLK, 320>>>(feat, dist, coord, mu, sigma, ps);
    int mtiles = (n_atoms * 4 + BM64 - 1) / BM64;
    gemm_kernel<<<mtiles, 256, 2 * STG_BYTES>>>(selfb, vecs, out, n_atoms);
}

// round 15
// speedup vs baseline: 1.5860x; 1.0191x over previous
#include <cuda_runtime.h>
#include <cuda_bf16.h>
#include <cstdint>

typedef unsigned long long ull;

#define HARD_CUT 6.5f
#define PI_F 3.14159265358979f

#define KTOT 1728            // 1600 scalar + 80 self + 48 zero pad (27*64)
#define KCH  64
#define NCH  27
#define MPAD 20096           // 314*64
#define ATOMS_PER_BLK 4

// smem stage layout (bytes, per buffer) — BM=64 tiles, 3-stage pipeline
#define BM64   64
#define OFF_AH 0
#define OFF_AL 8192
#define OFF_BH 16384
#define OFF_BL 26624
#define STG_BYTES 36864
#define NSTAGE 3

// ---------------- scratch (static __device__, zero-init => pad rows/cols stay 0) ----
__device__ __align__(16) __nv_bfloat16 g_env_hi[(size_t)MPAD * KTOT];
__device__ __align__(16) __nv_bfloat16 g_env_lo[(size_t)MPAD * KTOT];
__device__ __align__(16) __nv_bfloat16 g_w2h[80 * KTOT];   // B[N=80][K] K-major
__device__ __align__(16) __nv_bfloat16 g_w2l[80 * KTOT];
__device__ int g_seg[5008];                                // segment starts per atom

// ---------------- helpers ----------------
__device__ __forceinline__ int lower_bound_i(const int* __restrict__ arr, int n, int val) {
    int lo = 0, hi = n;
    while (lo < hi) { int mid = (lo + hi) >> 1; if (arr[mid] < val) lo = mid + 1; else hi = mid; }
    return lo;
}
__device__ __forceinline__ uint32_t smem_u32(const void* p) {
    uint32_t a;
    asm("{ .reg .u64 t; cvta.to.shared.u64 t, %1; cvt.u32.u64 %0, t; }" : "=r"(a) : "l"(p));
    return a;
}
__device__ __forceinline__ void ldsm4(unsigned* r, uint32_t addr) {
    asm volatile("ldmatrix.sync.aligned.m8n8.x4.shared.b16 {%0,%1,%2,%3}, [%4];"
        : "=r"(r[0]), "=r"(r[1]), "=r"(r[2]), "=r"(r[3]) : "r"(addr));
}
__device__ __forceinline__ void ldsm2(unsigned* r, uint32_t addr) {
    asm volatile("ldmatrix.sync.aligned.m8n8.x2.shared.b16 {%0,%1}, [%2];"
        : "=r"(r[0]), "=r"(r[1]) : "r"(addr));
}
__device__ __forceinline__ void ldsm4t(unsigned* r, uint32_t addr) {
    asm volatile("ldmatrix.sync.aligned.m8n8.x4.trans.shared.b16 {%0,%1,%2,%3}, [%4];"
        : "=r"(r[0]), "=r"(r[1]), "=r"(r[2]), "=r"(r[3]) : "r"(addr));
}
__device__ __forceinline__ void ldsm2t(unsigned* r, uint32_t addr) {
    asm volatile("ldmatrix.sync.aligned.m8n8.x2.trans.shared.b16 {%0,%1}, [%2];"
        : "=r"(r[0]), "=r"(r[1]) : "r"(addr));
}
__device__ __forceinline__ void mma16816(float* d, const unsigned* a, const unsigned* b) {
    asm volatile("mma.sync.aligned.m16n8k16.row.col.f32.bf16.bf16.f32 "
        "{%0,%1,%2,%3}, {%4,%5,%6,%7}, {%8,%9}, {%0,%1,%2,%3};"
        : "+f"(d[0]), "+f"(d[1]), "+f"(d[2]), "+f"(d[3])
        : "r"(a[0]), "r"(a[1]), "r"(a[2]), "r"(a[3]), "r"(b[0]), "r"(b[1]));
}
#define CP16(dst, src)  asm volatile("cp.async.cg.shared.global [%0], [%1], 16;" :: "r"(dst), "l"(src) : "memory")
#define CP_COMMIT()     asm volatile("cp.async.commit_group;" ::: "memory")
#define CP_WAIT2()      asm volatile("cp.async.wait_group 2;" ::: "memory")
#define CP_WAIT1()      asm volatile("cp.async.wait_group 1;" ::: "memory")
#define CP_WAIT0()      asm volatile("cp.async.wait_group 0;" ::: "memory")

// ---------------- K0a: W2 -> bf16 hi/lo, [80 o][1728 k] K-major ----------------
__global__ void build_w_kernel(const float* __restrict__ iw, const float* __restrict__ selfw) {
    int idx = blockIdx.x * blockDim.x + threadIdx.x;
    if (idx >= 80 * KTOT) return;
    int o = idx / KTOT, k = idx % KTOT;
    float v = 0.0f;
    if (k < 1600)      { int s = k / 80, f = k % 80; v = iw[s * 6400 + o * 80 + f]; }
    else if (k < 1680) { v = selfw[o * 80 + (k - 1600)]; }
    __nv_bfloat16 h = __float2bfloat16(v);
    __nv_bfloat16 l = __float2bfloat16(v - __bfloat162float(h));
    g_w2h[idx] = h;
    g_w2l[idx] = l;
}

// ---------------- K0b: segment boundaries ----------------
__global__ void seg_kernel(const int* __restrict__ pf, int n_pairs, int n_atoms) {
    int a = blockIdx.x * blockDim.x + threadIdx.x;
    if (a <= n_atoms) g_seg[a] = lower_bound_i(pf, n_pairs, a);
}

// ---------------- K1: envsum via mma.sync, double-buffered tiles, 2 CTAs/SM ----------
#define CF_STRIDE 88
#define CF_ELEMS  (16 * CF_STRIDE)
#define CF_BYTES  (CF_ELEMS * 2)

__device__ __forceinline__ void flush_mma(float acc[5][4], int a, int cs0, int f0w, int lane) {
    int r0 = cs0 + (lane >> 2);
    int fb = f0w + (lane & 3) * 2;
    #pragma unroll
    for (int nt = 0; nt < 5; nt++) {
        int f = fb + nt * 8;
        #pragma unroll
        for (int h = 0; h < 2; h++) {
            int row = r0 + h * 8;
            float v0 = acc[nt][2 * h], v1 = acc[nt][2 * h + 1];
            int c = row / 20, s = row % 20;
            size_t idx = (size_t)(a * 4 + c) * KTOT + s * 80 + f;
            __nv_bfloat16 h0 = __float2bfloat16(v0);
            __nv_bfloat16 l0 = __float2bfloat16(v0 - __bfloat162float(h0));
            __nv_bfloat16 h1 = __float2bfloat16(v1);
            __nv_bfloat16 l1 = __float2bfloat16(v1 - __bfloat162float(h1));
            __nv_bfloat162 hh; hh.x = h0; hh.y = h1;
            __nv_bfloat162 ll; ll.x = l0; ll.y = l1;
            *(__nv_bfloat162*)&g_env_hi[idx] = hh;
            *(__nv_bfloat162*)&g_env_lo[idx] = ll;
            acc[nt][2 * h] = 0.0f;
            acc[nt][2 * h + 1] = 0.0f;
        }
    }
}

__global__ __launch_bounds__(320, 2) void envsum_kernel(
    const float* __restrict__ feat, const float* __restrict__ dist,
    const float* __restrict__ coord, const float* __restrict__ mu,
    const float* __restrict__ sigma, const int* __restrict__ ps)
{
    __shared__ __align__(16) __nv_bfloat16 s_cfH[2 * CF_ELEMS];
    __shared__ __align__(16) __nv_bfloat16 s_cfL[2 * CF_ELEMS];
    __shared__ __align__(16) __nv_bfloat16 s_ftH[2 * CF_ELEMS];
    __shared__ __align__(16) __nv_bfloat16 s_ftL[2 * CF_ELEMS];

    int a0  = blockIdx.x * ATOMS_PER_BLK;
    int tid = threadIdx.x;
    int lane = tid & 31, wid = tid >> 5;

    int segs[ATOMS_PER_BLK + 1];
    #pragma unroll
    for (int i = 0; i <= ATOMS_PER_BLK; i++) segs[i] = g_seg[a0 + i];
    int cum[ATOMS_PER_BLK + 1];
    cum[0] = 0;
    #pragma unroll
    for (int i = 0; i < ATOMS_PER_BLK; i++)
        cum[i + 1] = cum[i] + ((segs[i + 1] - segs[i] + 15) >> 4);
    int T = cum[ATOMS_PER_BLK];

    // consumer roles
    int mw = wid % 5, nw = wid / 5;
    int cs0 = mw * 16, f0w = nw * 40;
    uint32_t uCfH = smem_u32(s_cfH), uCfL = smem_u32(s_cfL);
    uint32_t uFtH = smem_u32(s_ftH), uFtL = smem_u32(s_ftL);
    int krowA = (lane & 7) + ((lane >> 4) & 1) * 8;
    int krowB = (lane & 7) + ((lane >> 3) & 1) * 8;
    uint32_t aoff  = (uint32_t)(krowA * (CF_STRIDE * 2) + (cs0 + ((lane >> 3) & 1) * 8) * 2);
    uint32_t boff0 = (uint32_t)(krowB * (CF_STRIDE * 2) + (f0w + ((lane >> 4) & 1) * 8) * 2);
    uint32_t boff1 = boff0 + 32;
    uint32_t boff2 = (uint32_t)(krowB * (CF_STRIDE * 2) + (f0w + 32) * 2);

    float acc[5][4];
    #pragma unroll
    for (int nt = 0; nt < 5; nt++)
        #pragma unroll
        for (int q = 0; q < 4; q++) acc[nt][q] = 0.0f;

    // producer roles
    int pp = tid / 20;
    int j  = tid - pp * 20;
    float muj = mu[j];
    float isj = 1.0f / sigma[j];

    // prefetch chunk 0
    float nd = 1.0f, nx = 0.f, ny = 0.f, nz = 0.f;
    float4 nf = make_float4(0.f, 0.f, 0.f, 0.f);
    int have = 0;
    if (T > 0) {
        int at = 0;
        while (at < ATOMS_PER_BLK - 1 && 0 >= cum[at + 1]) at++;
        int p = segs[at] + pp;
        if (p < segs[at + 1]) {
            nd = dist[p]; nx = coord[3 * p]; ny = coord[3 * p + 1]; nz = coord[3 * p + 2];
            int r = ps[p]; nf = ((const float4*)feat)[r * 20 + j];
            have = 1;
        }
    }

    int cur_at = 0;
    for (int t = 0; t < T; t++) {
        while (cur_at < ATOMS_PER_BLK - 1 && t >= cum[cur_at + 1]) cur_at++;
        int bsel = t & 1;
        uint32_t bofs = (uint32_t)(bsel * CF_BYTES);
        __nv_bfloat16* cfH = s_cfH + bsel * CF_ELEMS;
        __nv_bfloat16* cfL = s_cfL + bsel * CF_ELEMS;
        __nv_bfloat16* ftH = s_ftH + bsel * CF_ELEMS;
        __nv_bfloat16* ftL = s_ftL + bsel * CF_ELEMS;

        // produce chunk t into buffer bsel
        {
            float c0 = 0.f, c1 = 0.f, c2 = 0.f, c3 = 0.f;
            float4 fv = make_float4(0.f, 0.f, 0.f, 0.f);
            if (have) {
                float inv = 1.0f / nd;
                float cut = (nd < HARD_CUT) ? 0.5f * (__cosf(PI_F * nd * (1.0f / HARD_CUT)) + 1.0f) : 0.0f;
                float z   = (inv - muj) * isj;
                float e   = __expf(-0.5f * z * z) * cut;
                c0 = e; c1 = e * nx * inv; c2 = e * ny * inv; c3 = e * nz * inv;
                fv = nf;
            }
            int cb = pp * CF_STRIDE + j;
            float cv[4] = {c0, c1, c2, c3};
            #pragma unroll
            for (int cc = 0; cc < 4; cc++) {
                __nv_bfloat16 h = __float2bfloat16(cv[cc]);
                __nv_bfloat16 l = __float2bfloat16(cv[cc] - __bfloat162float(h));
                cfH[cb + cc * 20] = h;
                cfL[cb + cc * 20] = l;
            }
            __nv_bfloat16 fh[4], fl[4];
            float fa[4] = {fv.x, fv.y, fv.z, fv.w};
            #pragma unroll
            for (int q = 0; q < 4; q++) {
                fh[q] = __float2bfloat16(fa[q]);
                fl[q] = __float2bfloat16(fa[q] - __bfloat162float(fh[q]));
            }
            int fb = pp * CF_STRIDE + j * 4;
            __nv_bfloat162 p0; p0.x = fh[0]; p0.y = fh[1];
            __nv_bfloat162 p1; p1.x = fh[2]; p1.y = fh[3];
            __nv_bfloat162 q0; q0.x = fl[0]; q0.y = fl[1];
            __nv_bfloat162 q1; q1.x = fl[2]; q1.y = fl[3];
            *(__nv_bfloat162*)&ftH[fb]     = p0;
            *(__nv_bfloat162*)&ftH[fb + 2] = p1;
            *(__nv_bfloat162*)&ftL[fb]     = q0;
            *(__nv_bfloat162*)&ftL[fb + 2] = q1;
        }
        __syncthreads();                    // tiles ready (single barrier per chunk)

        // prefetch chunk t+1 (overlaps consume)
        have = 0;
        nf = make_float4(0.f, 0.f, 0.f, 0.f);
        if (t + 1 < T) {
            int at2 = cur_at;
            while (at2 < ATOMS_PER_BLK - 1 && t + 1 >= cum[at2 + 1]) at2++;
            int p = segs[at2] + (t + 1 - cum[at2]) * 16 + pp;
            if (p < segs[at2 + 1]) {
                nd = dist[p]; nx = coord[3 * p]; ny = coord[3 * p + 1]; nz = coord[3 * p + 2];
                int r = ps[p]; nf = ((const float4*)feat)[r * 20 + j];
                have = 1;
            }
        }

        // consume: ldsm.trans + 15 mma
        {
            unsigned aH[4], aL[4], bH[10], bL[10];
            ldsm4t(aH, uCfH + bofs + aoff);
            ldsm4t(aL, uCfL + bofs + aoff);
            ldsm4t(bH + 0, uFtH + bofs + boff0);
            ldsm4t(bH + 4, uFtH + bofs + boff1);
            ldsm2t(bH + 8, uFtH + bofs + boff2);
            ldsm4t(bL + 0, uFtL + bofs + boff0);
            ldsm4t(bL + 4, uFtL + bofs + boff1);
            ldsm2t(bL + 8, uFtL + bofs + boff2);
            #pragma unroll
            for (int nt = 0; nt < 5; nt++) {
                mma16816(acc[nt], aH, bH + 2 * nt);
                mma16816(acc[nt], aL, bH + 2 * nt);
                mma16816(acc[nt], aH, bL + 2 * nt);
            }
        }

        if (t == cum[cur_at + 1] - 1)
            flush_mma(acc, a0 + cur_at, cs0, f0w, lane);
    }

    #pragma unroll
    for (int i = 0; i < ATOMS_PER_BLK; i++)
        if (cum[i + 1] == cum[i])
            flush_mma(acc, a0 + i, cs0, f0w, lane);

    // self-interaction rows: env[(a,c), 1600+f] = (c==0) ? feat[a,f] : 0
    {
        int c2 = tid / 80;   // 0..3
        int f  = tid % 80;
        #pragma unroll
        for (int ai = 0; ai < ATOMS_PER_BLK; ai++) {
            int a = a0 + ai;
            float v = (c2 == 0) ? feat[a * 80 + f] : 0.0f;
            __nv_bfloat16 h = __float2bfloat16(v);
            __nv_bfloat16 l = __float2bfloat16(v - __bfloat162float(h));
            size_t off = (size_t)(a * 4 + c2) * KTOT + 1600 + f;
            g_env_hi[off] = h;
            g_env_lo[off] = l;
        }
    }
}

// ---------------- K2: bf16-split GEMM, BM=64, 3-stage pipeline, k-split warps ------
__device__ __forceinline__ void load_stage(uint32_t sstage, int m0, int kc, int tid) {
    #pragma unroll
    for (int i = 0; i < 2; i++) {
        int u = tid + i * 256;                 // 512: 64 rows x 8 segs
        int r = u >> 3, sg = u & 7;
        uint32_t so = (uint32_t)(r * 128 + ((sg ^ (r & 7)) * 16));
        const char* gh = (const char*)(g_env_hi + (size_t)(m0 + r) * KTOT + kc) + sg * 16;
        const char* gl = (const char*)(g_env_lo + (size_t)(m0 + r) * KTOT + kc) + sg * 16;
        CP16(sstage + OFF_AH + so, gh);
        CP16(sstage + OFF_AL + so, gl);
    }
    #pragma unroll
    for (int i = 0; i < 3; i++) {
        int u = tid + i * 256;                 // 640: 80 rows x 8 segs
        if (u < 640) {
            int r = u >> 3, sg = u & 7;
            uint32_t so = (uint32_t)(r * 128 + ((sg ^ (r & 7)) * 16));
            const char* gh = (const char*)(g_w2h + (size_t)r * KTOT + kc) + sg * 16;
            const char* gl = (const char*)(g_w2l + (size_t)r * KTOT + kc) + sg * 16;
            CP16(sstage + OFF_BH + so, gh);
            CP16(sstage + OFF_BL + so, gl);
        }
    }
}

__global__ __launch_bounds__(256, 2)
void gemm_kernel(const float* __restrict__ selfb, const float* __restrict__ vecs,
                 float* __restrict__ out, int n_atoms)
{
    extern __shared__ __align__(1024) char smem[];
    uint32_t sb = smem_u32(smem);
    int tid  = threadIdx.x;
    int lane = tid & 31;
    int wid  = tid >> 5;
    int m0   = blockIdx.x * BM64;

    int wg = wid >> 2;            // k-group: ks in {2*wg, 2*wg+1}
    int wi = wid & 3;
    int m0w = (wi >> 1) * 32;
    int n0w = (wi & 1) * 40;
    int ksBase = wg * 2;

    int rA_loc = (lane & 7) + ((lane >> 3) & 1) * 8;
    uint32_t rowA0 = (uint32_t)((m0w + rA_loc) * 128);
    uint32_t rowA1 = rowA0 + 16 * 128;
    int rB_loc = (lane & 7) + ((lane >> 4) & 1) * 8;
    uint32_t rowB0 = (uint32_t)((n0w + rB_loc) * 128);
    uint32_t rowB1 = rowB0 + 16 * 128;
    uint32_t rowB2 = (uint32_t)((n0w + 32 + (lane & 7)) * 128);

    float acc[2][5][4];
    #pragma unroll
    for (int mt = 0; mt < 2; mt++)
        #pragma unroll
        for (int nt = 0; nt < 5; nt++)
            #pragma unroll
            for (int q = 0; q < 4; q++) acc[mt][nt][q] = 0.0f;

    load_stage(sb, m0, 0, tid);                     CP_COMMIT();
    load_stage(sb + STG_BYTES, m0, KCH, tid);       CP_COMMIT();
    load_stage(sb + 2 * STG_BYTES, m0, 2 * KCH, tid); CP_COMMIT();

    for (int c = 0; c < NCH; c++) {
        if (c < NCH - 2) CP_WAIT2();
        else if (c == NCH - 2) CP_WAIT1();
        else CP_WAIT0();
        __syncthreads();

        uint32_t st  = sb + (uint32_t)((c % NSTAGE) * STG_BYTES);
        uint32_t sAH = st + OFF_AH, sAL = st + OFF_AL;
        uint32_t sBH = st + OFF_BH, sBL = st + OFF_BL;

        #pragma unroll
        for (int kss = 0; kss < 2; kss++) {
            int ks = ksBase + kss;
            uint32_t swA = (uint32_t)((((ks * 2) + (lane >> 4)) ^ (lane & 7)) * 16);
            uint32_t swB = (uint32_t)((((ks * 2) + ((lane >> 3) & 1)) ^ (lane & 7)) * 16);
            unsigned aH[2][4], aL[2][4], bH[10], bL[10];
            ldsm4(aH[0], sAH + rowA0 + swA);
            ldsm4(aH[1], sAH + rowA1 + swA);
            ldsm4(aL[0], sAL + rowA0 + swA);
            ldsm4(aL[1], sAL + rowA1 + swA);
            ldsm4(bH + 0, sBH + rowB0 + swB);
            ldsm4(bH + 4, sBH + rowB1 + swB);
            ldsm2(bH + 8, sBH + rowB2 + swB);
            ldsm4(bL + 0, sBL + rowB0 + swB);
            ldsm4(bL + 4, sBL + rowB1 + swB);
            ldsm2(bL + 8, sBL + rowB2 + swB);
            #pragma unroll
            for (int mt = 0; mt < 2; mt++)
                #pragma unroll
                for (int nt = 0; nt < 5; nt++) {
                    mma16816(acc[mt][nt], aH[mt], bH + 2 * nt);
                    mma16816(acc[mt][nt], aL[mt], bH + 2 * nt);
                    mma16816(acc[mt][nt], aH[mt], bL + 2 * nt);
                }
        }
        __syncthreads();
        if (c + 3 < NCH) {
            load_stage(sb + (uint32_t)((c % NSTAGE) * STG_BYTES), m0, (c + 3) * KCH, tid);
            CP_COMMIT();
        }
    }

    // merge k-split partials through C[64][80] in smem
    float* C = (float*)smem;
    int grp  = lane >> 2;
    int col0 = (lane & 3) * 2;
    if (wg == 1) {
        #pragma unroll
        for (int mt = 0; mt < 2; mt++) {
            int r0 = m0w + mt * 16 + grp;
            #pragma unroll
            for (int nt = 0; nt < 5; nt++) {
                int cc = n0w + nt * 8 + col0;
                *(float2*)&C[r0 * 80 + cc]       = make_float2(acc[mt][nt][0], acc[mt][nt][1]);
                *(float2*)&C[(r0 + 8) * 80 + cc] = make_float2(acc[mt][nt][2], acc[mt][nt][3]);
            }
        }
    }
    __syncthreads();
    if (wg == 0) {
        #pragma unroll
        for (int mt = 0; mt < 2; mt++) {
            int r0 = m0w + mt * 16 + grp;
            #pragma unroll
            for (int nt = 0; nt < 5; nt++) {
                int cc = n0w + nt * 8 + col0;
                float2 v0 = *(float2*)&C[r0 * 80 + cc];
                float2 v1 = *(float2*)&C[(r0 + 8) * 80 + cc];
                v0.x += acc[mt][nt][0]; v0.y += acc[mt][nt][1];
                v1.x += acc[mt][nt][2]; v1.y += acc[mt][nt][3];
                *(float2*)&C[r0 * 80 + cc]       = v0;
                *(float2*)&C[(r0 + 8) * 80 + cc] = v1;
            }
        }
    }
    __syncthreads();

    #pragma unroll
    for (int u = tid; u < 1280; u += 256) {
        int al = u / 80, o = u % 80;
        int a = (m0 >> 2) + al;
        if (a < n_atoms) {
            float s0 = C[(al * 4 + 0) * 80 + o];
            float x  = C[(al * 4 + 1) * 80 + o];
            float y  = C[(al * 4 + 2) * 80 + o];
            float z  = C[(al * 4 + 3) * 80 + o];
            out[a * 80 + o] = s0 + selfb[o]
                + vecs[o] * sqrtf(fmaf(x, x, fmaf(y, y, z * z)) + 1e-30f);
        }
    }
}

// ---------------- launch ----------------
extern "C" void kernel_launch(void* const* d_in, const int* in_sizes, int n_in,
                              void* d_out, int out_size) {
    const float* feat  = (const float*)d_in[0];
    const float* dist  = (const float*)d_in[1];
    const float* coord = (const float*)d_in[2];
    const float* iw    = (const float*)d_in[3];
    const float* selfw = (const float*)d_in[4];
    const float* selfb = (const float*)d_in[5];
    const float* vecs  = (const float*)d_in[6];
    const float* mu    = (const float*)d_in[7];
    const float* sigma = (const float*)d_in[8];
    const int*   pf    = (const int*)d_in[9];
    const int*   ps    = (const int*)d_in[10];
    int n_pairs = in_sizes[9];
    int n_atoms = in_sizes[0] / 80;
    float* out = (float*)d_out;

    static int smem_set = 0;
    if (!smem_set) {
        cudaFuncSetAttribute(gemm_kernel, cudaFuncAttributeMaxDynamicSharedMemorySize,
                             NSTAGE * STG_BYTES);
        smem_set = 1;
    }

    build_w_kernel<<<(80 * KTOT + 255) / 256, 256>>>(iw, selfw);
    seg_kernel<<<(n_atoms + 256) / 256, 256>>>(pf, n_pairs, n_atoms);
    envsum_kernel<<<n_atoms / ATOMS_PER_BLK, 320>>>(feat, dist, coord, mu, sigma, ps);
    int mtiles = (n_atoms * 4 + BM64 - 1) / BM64;
    gemm_kernel<<<mtiles, 256, NSTAGE * STG_BYTES>>>(selfb, vecs, out, n_atoms);
}

// round 16
// speedup vs baseline: 2.3067x; 1.4544x over previous
#include <cuda_runtime.h>
#include <cuda_fp16.h>
#include <cstdint>

typedef unsigned long long ull;

#define HARD_CUT 6.5f
#define PI_F 3.14159265358979f

#define KTOT 1728            // 1600 scalar + 80 self + 48 zero pad (27*64)
#define KCH  64
#define NCH  27
#define MPAD 20096           // 314*64
#define ATOMS_PER_BLK 4

// smem stage layout (bytes, per buffer) — BM=64 tiles, fp16 single-plane A
#define BM64   64
#define OFF_AF 0
#define OFF_BH 8192
#define OFF_BL 18432
#define STG_BYTES 28672
#define NSTAGE 3

// ---------------- scratch (static __device__, zero-init => pad rows/cols stay 0) ----
__device__ __align__(16) __half g_env_f16[(size_t)MPAD * KTOT];   // 69.5 MB
__device__ __align__(16) __half g_w2h[80 * KTOT];   // W fp16 hi, [80 o][1728 k] K-major
__device__ __align__(16) __half g_w2l[80 * KTOT];   // W fp16 lo
__device__ int g_seg[5008];                         // segment starts per atom

// ---------------- helpers ----------------
__device__ __forceinline__ int lower_bound_i(const int* __restrict__ arr, int n, int val) {
    int lo = 0, hi = n;
    while (lo < hi) { int mid = (lo + hi) >> 1; if (arr[mid] < val) lo = mid + 1; else hi = mid; }
    return lo;
}
__device__ __forceinline__ uint32_t smem_u32(const void* p) {
    uint32_t a;
    asm("{ .reg .u64 t; cvta.to.shared.u64 t, %1; cvt.u32.u64 %0, t; }" : "=r"(a) : "l"(p));
    return a;
}
__device__ __forceinline__ void ldsm4(unsigned* r, uint32_t addr) {
    asm volatile("ldmatrix.sync.aligned.m8n8.x4.shared.b16 {%0,%1,%2,%3}, [%4];"
        : "=r"(r[0]), "=r"(r[1]), "=r"(r[2]), "=r"(r[3]) : "r"(addr));
}
__device__ __forceinline__ void ldsm2(unsigned* r, uint32_t addr) {
    asm volatile("ldmatrix.sync.aligned.m8n8.x2.shared.b16 {%0,%1}, [%2];"
        : "=r"(r[0]), "=r"(r[1]) : "r"(addr));
}
__device__ __forceinline__ void ldsm4t(unsigned* r, uint32_t addr) {
    asm volatile("ldmatrix.sync.aligned.m8n8.x4.trans.shared.b16 {%0,%1,%2,%3}, [%4];"
        : "=r"(r[0]), "=r"(r[1]), "=r"(r[2]), "=r"(r[3]) : "r"(addr));
}
__device__ __forceinline__ void ldsm2t(unsigned* r, uint32_t addr) {
    asm volatile("ldmatrix.sync.aligned.m8n8.x2.trans.shared.b16 {%0,%1}, [%2];"
        : "=r"(r[0]), "=r"(r[1]) : "r"(addr));
}
__device__ __forceinline__ void mma16816f(float* d, const unsigned* a, const unsigned* b) {
    asm volatile("mma.sync.aligned.m16n8k16.row.col.f32.f16.f16.f32 "
        "{%0,%1,%2,%3}, {%4,%5,%6,%7}, {%8,%9}, {%0,%1,%2,%3};"
        : "+f"(d[0]), "+f"(d[1]), "+f"(d[2]), "+f"(d[3])
        : "r"(a[0]), "r"(a[1]), "r"(a[2]), "r"(a[3]), "r"(b[0]), "r"(b[1]));
}
#define CP16(dst, src)  asm volatile("cp.async.cg.shared.global [%0], [%1], 16;" :: "r"(dst), "l"(src) : "memory")
#define CP_COMMIT()     asm volatile("cp.async.commit_group;" ::: "memory")
#define CP_WAIT2()      asm volatile("cp.async.wait_group 2;" ::: "memory")
#define CP_WAIT1()      asm volatile("cp.async.wait_group 1;" ::: "memory")
#define CP_WAIT0()      asm volatile("cp.async.wait_group 0;" ::: "memory")

// ---------------- K0a: W2 -> fp16 hi/lo, [80 o][1728 k] K-major ----------------
__global__ void build_w_kernel(const float* __restrict__ iw, const float* __restrict__ selfw) {
    int idx = blockIdx.x * blockDim.x + threadIdx.x;
    if (idx >= 80 * KTOT) return;
    int o = idx / KTOT, k = idx % KTOT;
    float v = 0.0f;
    if (k < 1600)      { int s = k / 80, f = k % 80; v = iw[s * 6400 + o * 80 + f]; }
    else if (k < 1680) { v = selfw[o * 80 + (k - 1600)]; }
    __half h = __float2half_rn(v);
    __half l = __float2half_rn(v - __half2float(h));
    g_w2h[idx] = h;
    g_w2l[idx] = l;
}

// ---------------- K0b: segment boundaries ----------------
__global__ void seg_kernel(const int* __restrict__ pf, int n_pairs, int n_atoms) {
    int a = blockIdx.x * blockDim.x + threadIdx.x;
    if (a <= n_atoms) g_seg[a] = lower_bound_i(pf, n_pairs, a);
}

// ---------------- K1: envsum via fp16 mma.sync, double-buffered tiles ----------
// 4 atoms/block, 320 threads (10 warps). Per-atom chunks of 16 pairs.
// Producer: 20 lanes/pair -> coef[16][80], feat[16][80] as single fp16 (stride 88).
// Consumer: warp (mw=wid%5, nw=wid/5) owns cs [mw*16,+16) x f [nw*40,+40); 1-pass mma.
#define CF_STRIDE 88
#define CF_ELEMS  (16 * CF_STRIDE)
#define CF_BYTES  (CF_ELEMS * 2)

__device__ __forceinline__ void flush_mma(float acc[5][4], int a, int cs0, int f0w, int lane) {
    int r0 = cs0 + (lane >> 2);
    int fb = f0w + (lane & 3) * 2;
    #pragma unroll
    for (int nt = 0; nt < 5; nt++) {
        int f = fb + nt * 8;
        #pragma unroll
        for (int h = 0; h < 2; h++) {
            int row = r0 + h * 8;
            int c = row / 20, s = row % 20;
            size_t idx = (size_t)(a * 4 + c) * KTOT + s * 80 + f;
            __half2 hv;
            hv.x = __float2half_rn(acc[nt][2 * h]);
            hv.y = __float2half_rn(acc[nt][2 * h + 1]);
            *(__half2*)&g_env_f16[idx] = hv;
            acc[nt][2 * h] = 0.0f;
            acc[nt][2 * h + 1] = 0.0f;
        }
    }
}

__global__ __launch_bounds__(320, 2) void envsum_kernel(
    const float* __restrict__ feat, const float* __restrict__ dist,
    const float* __restrict__ coord, const float* __restrict__ mu,
    const float* __restrict__ sigma, const int* __restrict__ ps)
{
    __shared__ __align__(16) __half s_cfF[2 * CF_ELEMS];
    __shared__ __align__(16) __half s_ftF[2 * CF_ELEMS];

    int a0  = blockIdx.x * ATOMS_PER_BLK;
    int tid = threadIdx.x;
    int lane = tid & 31, wid = tid >> 5;

    int segs[ATOMS_PER_BLK + 1];
    #pragma unroll
    for (int i = 0; i <= ATOMS_PER_BLK; i++) segs[i] = g_seg[a0 + i];
    int cum[ATOMS_PER_BLK + 1];
    cum[0] = 0;
    #pragma unroll
    for (int i = 0; i < ATOMS_PER_BLK; i++)
        cum[i + 1] = cum[i] + ((segs[i + 1] - segs[i] + 15) >> 4);
    int T = cum[ATOMS_PER_BLK];

    // consumer roles
    int mw = wid % 5, nw = wid / 5;
    int cs0 = mw * 16, f0w = nw * 40;
    uint32_t uCfF = smem_u32(s_cfF);
    uint32_t uFtF = smem_u32(s_ftF);
    int krowA = (lane & 7) + ((lane >> 4) & 1) * 8;
    int krowB = (lane & 7) + ((lane >> 3) & 1) * 8;
    uint32_t aoff  = (uint32_t)(krowA * (CF_STRIDE * 2) + (cs0 + ((lane >> 3) & 1) * 8) * 2);
    uint32_t boff0 = (uint32_t)(krowB * (CF_STRIDE * 2) + (f0w + ((lane >> 4) & 1) * 8) * 2);
    uint32_t boff1 = boff0 + 32;
    uint32_t boff2 = (uint32_t)(krowB * (CF_STRIDE * 2) + (f0w + 32) * 2);

    float acc[5][4];
    #pragma unroll
    for (int nt = 0; nt < 5; nt++)
        #pragma unroll
        for (int q = 0; q < 4; q++) acc[nt][q] = 0.0f;

    // producer roles
    int pp = tid / 20;
    int j  = tid - pp * 20;
    float muj = mu[j];
    float isj = 1.0f / sigma[j];

    // prefetch chunk 0
    float nd = 1.0f, nx = 0.f, ny = 0.f, nz = 0.f;
    float4 nf = make_float4(0.f, 0.f, 0.f, 0.f);
    int have = 0;
    if (T > 0) {
        int at = 0;
        while (at < ATOMS_PER_BLK - 1 && 0 >= cum[at + 1]) at++;
        int p = segs[at] + pp;
        if (p < segs[at + 1]) {
            nd = dist[p]; nx = coord[3 * p]; ny = coord[3 * p + 1]; nz = coord[3 * p + 2];
            int r = ps[p]; nf = ((const float4*)feat)[r * 20 + j];
            have = 1;
        }
    }

    int cur_at = 0;
    for (int t = 0; t < T; t++) {
        while (cur_at < ATOMS_PER_BLK - 1 && t >= cum[cur_at + 1]) cur_at++;
        int bsel = t & 1;
        uint32_t bofs = (uint32_t)(bsel * CF_BYTES);
        __half* cfF = s_cfF + bsel * CF_ELEMS;
        __half* ftF = s_ftF + bsel * CF_ELEMS;

        // produce chunk t into buffer bsel
        {
            float c0 = 0.f, c1 = 0.f, c2 = 0.f, c3 = 0.f;
            float4 fv = make_float4(0.f, 0.f, 0.f, 0.f);
            if (have) {
                float inv = 1.0f / nd;
                float cut = (nd < HARD_CUT) ? 0.5f * (__cosf(PI_F * nd * (1.0f / HARD_CUT)) + 1.0f) : 0.0f;
                float z   = (inv - muj) * isj;
                float e   = __expf(-0.5f * z * z) * cut;
                c0 = e; c1 = e * nx * inv; c2 = e * ny * inv; c3 = e * nz * inv;
                fv = nf;
            }
            int cb = pp * CF_STRIDE + j;
            cfF[cb]      = __float2half_rn(c0);
            cfF[cb + 20] = __float2half_rn(c1);
            cfF[cb + 40] = __float2half_rn(c2);
            cfF[cb + 60] = __float2half_rn(c3);
            int fb = pp * CF_STRIDE + j * 4;
            __half2 f01, f23;
            f01.x = __float2half_rn(fv.x); f01.y = __float2half_rn(fv.y);
            f23.x = __float2half_rn(fv.z); f23.y = __float2half_rn(fv.w);
            *(__half2*)&ftF[fb]     = f01;
            *(__half2*)&ftF[fb + 2] = f23;
        }
        __syncthreads();                    // tiles ready (single barrier per chunk)

        // prefetch chunk t+1 (overlaps consume)
        have = 0;
        nf = make_float4(0.f, 0.f, 0.f, 0.f);
        if (t + 1 < T) {
            int at2 = cur_at;
            while (at2 < ATOMS_PER_BLK - 1 && t + 1 >= cum[at2 + 1]) at2++;
            int p = segs[at2] + (t + 1 - cum[at2]) * 16 + pp;
            if (p < segs[at2 + 1]) {
                nd = dist[p]; nx = coord[3 * p]; ny = coord[3 * p + 1]; nz = coord[3 * p + 2];
                int r = ps[p]; nf = ((const float4*)feat)[r * 20 + j];
                have = 1;
            }
        }

        // consume: ldsm.trans + 5 mma (single fp16 pass)
        {
            unsigned aF[4], bF[10];
            ldsm4t(aF, uCfF + bofs + aoff);
            ldsm4t(bF + 0, uFtF + bofs + boff0);
            ldsm4t(bF + 4, uFtF + bofs + boff1);
            ldsm2t(bF + 8, uFtF + bofs + boff2);
            #pragma unroll
            for (int nt = 0; nt < 5; nt++)
                mma16816f(acc[nt], aF, bF + 2 * nt);
        }

        if (t == cum[cur_at + 1] - 1)
            flush_mma(acc, a0 + cur_at, cs0, f0w, lane);
    }

    #pragma unroll
    for (int i = 0; i < ATOMS_PER_BLK; i++)
        if (cum[i + 1] == cum[i])
            flush_mma(acc, a0 + i, cs0, f0w, lane);

    // self-interaction rows: env[(a,c), 1600+f] = (c==0) ? feat[a,f] : 0
    {
        int c2 = tid / 80;   // 0..3
        int f  = tid % 80;
        #pragma unroll
        for (int ai = 0; ai < ATOMS_PER_BLK; ai++) {
            int a = a0 + ai;
            float v = (c2 == 0) ? feat[a * 80 + f] : 0.0f;
            g_env_f16[(size_t)(a * 4 + c2) * KTOT + 1600 + f] = __float2half_rn(v);
        }
    }
}

// ---------------- K2: fp16 GEMM, BM=64, 3-stage pipeline, k-split warps ----------
// A = env fp16 single plane; B = W fp16 hi/lo (2 passes). Epilogue fused.
__device__ __forceinline__ void load_stage(uint32_t sstage, int m0, int kc, int tid) {
    #pragma unroll
    for (int i = 0; i < 2; i++) {
        int u = tid + i * 256;                 // 512: 64 rows x 8 segs
        int r = u >> 3, sg = u & 7;
        uint32_t so = (uint32_t)(r * 128 + ((sg ^ (r & 7)) * 16));
        const char* ga = (const char*)(g_env_f16 + (size_t)(m0 + r) * KTOT + kc) + sg * 16;
        CP16(sstage + OFF_AF + so, ga);
    }
    #pragma unroll
    for (int i = 0; i < 3; i++) {
        int u = tid + i * 256;                 // 640: 80 rows x 8 segs
        if (u < 640) {
            int r = u >> 3, sg = u & 7;
            uint32_t so = (uint32_t)(r * 128 + ((sg ^ (r & 7)) * 16));
            const char* gh = (const char*)(g_w2h + (size_t)r * KTOT + kc) + sg * 16;
            const char* gl = (const char*)(g_w2l + (size_t)r * KTOT + kc) + sg * 16;
            CP16(sstage + OFF_BH + so, gh);
            CP16(sstage + OFF_BL + so, gl);
        }
    }
}

__global__ __launch_bounds__(256, 2)
void gemm_kernel(const float* __restrict__ selfb, const float* __restrict__ vecs,
                 float* __restrict__ out, int n_atoms)
{
    extern __shared__ __align__(1024) char smem[];
    uint32_t sb = smem_u32(smem);
    int tid  = threadIdx.x;
    int lane = tid & 31;
    int wid  = tid >> 5;
    int m0   = blockIdx.x * BM64;

    int wg = wid >> 2;            // k-group: ks in {2*wg, 2*wg+1}
    int wi = wid & 3;
    int m0w = (wi >> 1) * 32;
    int n0w = (wi & 1) * 40;
    int ksBase = wg * 2;

    int rA_loc = (lane & 7) + ((lane >> 3) & 1) * 8;
    uint32_t rowA0 = (uint32_t)((m0w + rA_loc) * 128);
    uint32_t rowA1 = rowA0 + 16 * 128;
    int rB_loc = (lane & 7) + ((lane >> 4) & 1) * 8;
    uint32_t rowB0 = (uint32_t)((n0w + rB_loc) * 128);
    uint32_t rowB1 = rowB0 + 16 * 128;
    uint32_t rowB2 = (uint32_t)((n0w + 32 + (lane & 7)) * 128);

    float acc[2][5][4];
    #pragma unroll
    for (int mt = 0; mt < 2; mt++)
        #pragma unroll
        for (int nt = 0; nt < 5; nt++)
            #pragma unroll
            for (int q = 0; q < 4; q++) acc[mt][nt][q] = 0.0f;

    load_stage(sb, m0, 0, tid);                       CP_COMMIT();
    load_stage(sb + STG_BYTES, m0, KCH, tid);         CP_COMMIT();
    load_stage(sb + 2 * STG_BYTES, m0, 2 * KCH, tid); CP_COMMIT();

    for (int c = 0; c < NCH; c++) {
        if (c < NCH - 2) CP_WAIT2();
        else if (c == NCH - 2) CP_WAIT1();
        else CP_WAIT0();
        __syncthreads();

        uint32_t st  = sb + (uint32_t)((c % NSTAGE) * STG_BYTES);
        uint32_t sAF = st + OFF_AF;
        uint32_t sBH = st + OFF_BH, sBL = st + OFF_BL;

        #pragma unroll
        for (int kss = 0; kss < 2; kss++) {
            int ks = ksBase + kss;
            uint32_t swA = (uint32_t)((((ks * 2) + (lane >> 4)) ^ (lane & 7)) * 16);
            uint32_t swB = (uint32_t)((((ks * 2) + ((lane >> 3) & 1)) ^ (lane & 7)) * 16);
            unsigned aF[2][4], bH[10], bL[10];
            ldsm4(aF[0], sAF + rowA0 + swA);
            ldsm4(aF[1], sAF + rowA1 + swA);
            ldsm4(bH + 0, sBH + rowB0 + swB);
            ldsm4(bH + 4, sBH + rowB1 + swB);
            ldsm2(bH + 8, sBH + rowB2 + swB);
            ldsm4(bL + 0, sBL + rowB0 + swB);
            ldsm4(bL + 4, sBL + rowB1 + swB);
            ldsm2(bL + 8, sBL + rowB2 + swB);
            #pragma unroll
            for (int mt = 0; mt < 2; mt++)
                #pragma unroll
                for (int nt = 0; nt < 5; nt++) {
                    mma16816f(acc[mt][nt], aF[mt], bH + 2 * nt);
                    mma16816f(acc[mt][nt], aF[mt], bL + 2 * nt);
                }
        }
        __syncthreads();
        if (c + 3 < NCH) {
            load_stage(sb + (uint32_t)((c % NSTAGE) * STG_BYTES), m0, (c + 3) * KCH, tid);
            CP_COMMIT();
        }
    }

    // merge k-split partials through C[64][80] in smem
    float* C = (float*)smem;
    int grp  = lane >> 2;
    int col0 = (lane & 3) * 2;
    if (wg == 1) {
        #pragma unroll
        for (int mt = 0; mt < 2; mt++) {
            int r0 = m0w + mt * 16 + grp;
            #pragma unroll
            for (int nt = 0; nt < 5; nt++) {
                int cc = n0w + nt * 8 + col0;
                *(float2*)&C[r0 * 80 + cc]       = make_float2(acc[mt][nt][0], acc[mt][nt][1]);
                *(float2*)&C[(r0 + 8) * 80 + cc] = make_float2(acc[mt][nt][2], acc[mt][nt][3]);
            }
        }
    }
    __syncthreads();
    if (wg == 0) {
        #pragma unroll
        for (int mt = 0; mt < 2; mt++) {
            int r0 = m0w + mt * 16 + grp;
            #pragma unroll
            for (int nt = 0; nt < 5; nt++) {
                int cc = n0w + nt * 8 + col0;
                float2 v0 = *(float2*)&C[r0 * 80 + cc];
                float2 v1 = *(float2*)&C[(r0 + 8) * 80 + cc];
                v0.x += acc[mt][nt][0]; v0.y += acc[mt][nt][1];
                v1.x += acc[mt][nt][2]; v1.y += acc[mt][nt][3];
                *(float2*)&C[r0 * 80 + cc]       = v0;
                *(float2*)&C[(r0 + 8) * 80 + cc] = v1;
            }
        }
    }
    __syncthreads();

    #pragma unroll
    for (int u = tid; u < 1280; u += 256) {
        int al = u / 80, o = u % 80;
        int a = (m0 >> 2) + al;
        if (a < n_atoms) {
            float s0 = C[(al * 4 + 0) * 80 + o];
            float x  = C[(al * 4 + 1) * 80 + o];
            float y  = C[(al * 4 + 2) * 80 + o];
            float z  = C[(al * 4 + 3) * 80 + o];
            out[a * 80 + o] = s0 + selfb[o]
                + vecs[o] * sqrtf(fmaf(x, x, fmaf(y, y, z * z)) + 1e-30f);
        }
    }
}

// ---------------- launch ----------------
extern "C" void kernel_launch(void* const* d_in, const int* in_sizes, int n_in,
                              void* d_out, int out_size) {
    const float* feat  = (const float*)d_in[0];
    const float* dist  = (const float*)d_in[1];
    const float* coord = (const float*)d_in[2];
    const float* iw    = (const float*)d_in[3];
    const float* selfw = (const float*)d_in[4];
    const float* selfb = (const float*)d_in[5];
    const float* vecs  = (const float*)d_in[6];
    const float* mu    = (const float*)d_in[7];
    const float* sigma = (const float*)d_in[8];
    const int*   pf    = (const int*)d_in[9];
    const int*   ps    = (const int*)d_in[10];
    int n_pairs = in_sizes[9];
    int n_atoms = in_sizes[0] / 80;
    float* out = (float*)d_out;

    static int smem_set = 0;
    if (!smem_set) {
        cudaFuncSetAttribute(gemm_kernel, cudaFuncAttributeMaxDynamicSharedMemorySize,
                             NSTAGE * STG_BYTES);
        smem_set = 1;
    }

    build_w_kernel<<<(80 * KTOT + 255) / 256, 256>>>(iw, selfw);
    seg_kernel<<<(n_atoms + 256) / 256, 256>>>(pf, n_pairs, n_atoms);
    envsum_kernel<<<n_atoms / ATOMS_PER_BLK, 320>>>(feat, dist, coord, mu, sigma, ps);
    int mtiles = (n_atoms * 4 + BM64 - 1) / BM64;
    gemm_kernel<<<mtiles, 256, NSTAGE * STG_BYTES>>>(selfb, vecs, out, n_atoms);
}

// round 17
// speedup vs baseline: 2.8008x; 1.2142x over previous
#include <cuda_runtime.h>
#include <cuda_fp16.h>
#include <cstdint>

typedef unsigned long long ull;

#define HARD_CUT 6.5f
#define PI_F 3.14159265358979f

#define KTOT 1728            // 1600 scalar + 80 self + 48 zero pad (27*64)
#define KCH  64
#define NCH  27
#define MPAD 20096           // 314*64
#define ATOMS_PER_BLK 4

// smem stage layout (bytes, per buffer) — BM=64 tiles, fp16 A + fp16 B (single plane)
#define BM64   64
#define OFF_AF 0
#define OFF_BH 8192
#define STG_BYTES 18432
#define NSTAGE 4

// ---------------- scratch (static __device__, zero-init => pad rows/cols stay 0) ----
__device__ __align__(16) __half g_env_f16[(size_t)MPAD * KTOT];   // 69.5 MB
__device__ __align__(16) __half g_w2[80 * KTOT];    // W fp16, [80 o][1728 k] K-major
__device__ int g_seg[5008];                         // segment starts per atom

// ---------------- helpers ----------------
__device__ __forceinline__ int lower_bound_i(const int* __restrict__ arr, int n, int val) {
    int lo = 0, hi = n;
    while (lo < hi) { int mid = (lo + hi) >> 1; if (arr[mid] < val) lo = mid + 1; else hi = mid; }
    return lo;
}
__device__ __forceinline__ uint32_t smem_u32(const void* p) {
    uint32_t a;
    asm("{ .reg .u64 t; cvta.to.shared.u64 t, %1; cvt.u32.u64 %0, t; }" : "=r"(a) : "l"(p));
    return a;
}
__device__ __forceinline__ void ldsm4(unsigned* r, uint32_t addr) {
    asm volatile("ldmatrix.sync.aligned.m8n8.x4.shared.b16 {%0,%1,%2,%3}, [%4];"
        : "=r"(r[0]), "=r"(r[1]), "=r"(r[2]), "=r"(r[3]) : "r"(addr));
}
__device__ __forceinline__ void ldsm2(unsigned* r, uint32_t addr) {
    asm volatile("ldmatrix.sync.aligned.m8n8.x2.shared.b16 {%0,%1}, [%2];"
        : "=r"(r[0]), "=r"(r[1]) : "r"(addr));
}
__device__ __forceinline__ void ldsm4t(unsigned* r, uint32_t addr) {
    asm volatile("ldmatrix.sync.aligned.m8n8.x4.trans.shared.b16 {%0,%1,%2,%3}, [%4];"
        : "=r"(r[0]), "=r"(r[1]), "=r"(r[2]), "=r"(r[3]) : "r"(addr));
}
__device__ __forceinline__ void ldsm2t(unsigned* r, uint32_t addr) {
    asm volatile("ldmatrix.sync.aligned.m8n8.x2.trans.shared.b16 {%0,%1}, [%2];"
        : "=r"(r[0]), "=r"(r[1]) : "r"(addr));
}
__device__ __forceinline__ void mma16816f(float* d, const unsigned* a, const unsigned* b) {
    asm volatile("mma.sync.aligned.m16n8k16.row.col.f32.f16.f16.f32 "
        "{%0,%1,%2,%3}, {%4,%5,%6,%7}, {%8,%9}, {%0,%1,%2,%3};"
        : "+f"(d[0]), "+f"(d[1]), "+f"(d[2]), "+f"(d[3])
        : "r"(a[0]), "r"(a[1]), "r"(a[2]), "r"(a[3]), "r"(b[0]), "r"(b[1]));
}
#define CP16(dst, src)  asm volatile("cp.async.cg.shared.global [%0], [%1], 16;" :: "r"(dst), "l"(src) : "memory")
#define CP_COMMIT()     asm volatile("cp.async.commit_group;" ::: "memory")
#define CP_WAIT3()      asm volatile("cp.async.wait_group 3;" ::: "memory")
#define CP_WAIT2()      asm volatile("cp.async.wait_group 2;" ::: "memory")
#define CP_WAIT1()      asm volatile("cp.async.wait_group 1;" ::: "memory")
#define CP_WAIT0()      asm volatile("cp.async.wait_group 0;" ::: "memory")

// ---------------- K0a: W2 -> fp16, [80 o][1728 k] K-major ----------------
__global__ void build_w_kernel(const float* __restrict__ iw, const float* __restrict__ selfw) {
    int idx = blockIdx.x * blockDim.x + threadIdx.x;
    if (idx >= 80 * KTOT) return;
    int o = idx / KTOT, k = idx % KTOT;
    float v = 0.0f;
    if (k < 1600)      { int s = k / 80, f = k % 80; v = iw[s * 6400 + o * 80 + f]; }
    else if (k < 1680) { v = selfw[o * 80 + (k - 1600)]; }
    g_w2[idx] = __float2half_rn(v);
}

// ---------------- K0b: segment boundaries ----------------
__global__ void seg_kernel(const int* __restrict__ pf, int n_pairs, int n_atoms) {
    int a = blockIdx.x * blockDim.x + threadIdx.x;
    if (a <= n_atoms) g_seg[a] = lower_bound_i(pf, n_pairs, a);
}

// ---------------- K1: envsum via fp16 mma.sync, 32-pair chunks ----------------
// 4 atoms/block, 320 threads (10 warps). Per-atom chunks of 32 pairs.
// Producer: 10 lanes/pair (pp=tid/10, jj=tid%10), each lane does senses jj & jj+10
// and feat quads jj & jj+10. Double-buffered tiles, one barrier per chunk.
// Consumer: warp (mw=wid%5, nw=wid/5) owns cs [mw*16,+16) x f [nw*40,+40);
// 2 k16-steps per chunk, single fp16 pass.
#define PCH 32
#define CF_STRIDE 88
#define CF_ELEMS  (PCH * CF_STRIDE)
#define CF_BYTES  (CF_ELEMS * 2)
#define STEP_BYTES (16 * CF_STRIDE * 2)

__device__ __forceinline__ void flush_mma(float acc[5][4], int a, int cs0, int f0w, int lane) {
    int r0 = cs0 + (lane >> 2);
    int fb = f0w + (lane & 3) * 2;
    #pragma unroll
    for (int nt = 0; nt < 5; nt++) {
        int f = fb + nt * 8;
        #pragma unroll
        for (int h = 0; h < 2; h++) {
            int row = r0 + h * 8;
            int c = row / 20, s = row % 20;
            size_t idx = (size_t)(a * 4 + c) * KTOT + s * 80 + f;
            __half2 hv;
            hv.x = __float2half_rn(acc[nt][2 * h]);
            hv.y = __float2half_rn(acc[nt][2 * h + 1]);
            *(__half2*)&g_env_f16[idx] = hv;
            acc[nt][2 * h] = 0.0f;
            acc[nt][2 * h + 1] = 0.0f;
        }
    }
}

__global__ __launch_bounds__(320, 2) void envsum_kernel(
    const float* __restrict__ feat, const float* __restrict__ dist,
    const float* __restrict__ coord, const float* __restrict__ mu,
    const float* __restrict__ sigma, const int* __restrict__ ps)
{
    __shared__ __align__(16) __half s_cfF[2 * CF_ELEMS];
    __shared__ __align__(16) __half s_ftF[2 * CF_ELEMS];

    int a0  = blockIdx.x * ATOMS_PER_BLK;
    int tid = threadIdx.x;
    int lane = tid & 31, wid = tid >> 5;

    int segs[ATOMS_PER_BLK + 1];
    #pragma unroll
    for (int i = 0; i <= ATOMS_PER_BLK; i++) segs[i] = g_seg[a0 + i];
    int cum[ATOMS_PER_BLK + 1];
    cum[0] = 0;
    #pragma unroll
    for (int i = 0; i < ATOMS_PER_BLK; i++)
        cum[i + 1] = cum[i] + ((segs[i + 1] - segs[i] + PCH - 1) >> 5);
    int T = cum[ATOMS_PER_BLK];

    // consumer roles
    int mw = wid % 5, nw = wid / 5;
    int cs0 = mw * 16, f0w = nw * 40;
    uint32_t uCfF = smem_u32(s_cfF);
    uint32_t uFtF = smem_u32(s_ftF);
    int krowA = (lane & 7) + ((lane >> 4) & 1) * 8;
    int krowB = (lane & 7) + ((lane >> 3) & 1) * 8;
    uint32_t aoff  = (uint32_t)(krowA * (CF_STRIDE * 2) + (cs0 + ((lane >> 3) & 1) * 8) * 2);
    uint32_t boff0 = (uint32_t)(krowB * (CF_STRIDE * 2) + (f0w + ((lane >> 4) & 1) * 8) * 2);
    uint32_t boff1 = boff0 + 32;
    uint32_t boff2 = (uint32_t)(krowB * (CF_STRIDE * 2) + (f0w + 32) * 2);

    float acc[5][4];
    #pragma unroll
    for (int nt = 0; nt < 5; nt++)
        #pragma unroll
        for (int q = 0; q < 4; q++) acc[nt][q] = 0.0f;

    // producer roles: 10 lanes per pair
    int pp = tid / 10;
    int jj = tid - pp * 10;
    float mu0 = mu[jj],       mu1 = mu[jj + 10];
    float is0 = 1.0f / sigma[jj], is1 = 1.0f / sigma[jj + 10];

    // prefetch chunk 0
    float nd = 1.0f, nx = 0.f, ny = 0.f, nz = 0.f;
    float4 nf0 = make_float4(0.f, 0.f, 0.f, 0.f);
    float4 nf1 = make_float4(0.f, 0.f, 0.f, 0.f);
    int have = 0;
    if (T > 0) {
        int at = 0;
        while (at < ATOMS_PER_BLK - 1 && 0 >= cum[at + 1]) at++;
        int p = segs[at] + pp;
        if (p < segs[at + 1]) {
            nd = dist[p]; nx = coord[3 * p]; ny = coord[3 * p + 1]; nz = coord[3 * p + 2];
            int r = ps[p];
            nf0 = ((const float4*)feat)[r * 20 + jj];
            nf1 = ((const float4*)feat)[r * 20 + jj + 10];
            have = 1;
        }
    }

    int cur_at = 0;
    for (int t = 0; t < T; t++) {
        while (cur_at < ATOMS_PER_BLK - 1 && t >= cum[cur_at + 1]) cur_at++;
        int bsel = t & 1;
        uint32_t bofs = (uint32_t)(bsel * CF_BYTES);
        __half* cfF = s_cfF + bsel * CF_ELEMS;
        __half* ftF = s_ftF + bsel * CF_ELEMS;

        // produce chunk t into buffer bsel (zeros on padding lanes)
        {
            float e0 = 0.f, e1 = 0.f;
            float ux = 0.f, uy = 0.f, uz = 0.f;
            float4 fv0 = make_float4(0.f, 0.f, 0.f, 0.f);
            float4 fv1 = make_float4(0.f, 0.f, 0.f, 0.f);
            if (have) {
                float inv = 1.0f / nd;
                float cut = (nd < HARD_CUT) ? 0.5f * (__cosf(PI_F * nd * (1.0f / HARD_CUT)) + 1.0f) : 0.0f;
                float z0  = (inv - mu0) * is0;
                float z1  = (inv - mu1) * is1;
                e0 = __expf(-0.5f * z0 * z0) * cut;
                e1 = __expf(-0.5f * z1 * z1) * cut;
                ux = nx * inv; uy = ny * inv; uz = nz * inv;
                fv0 = nf0; fv1 = nf1;
            }
            int cb = pp * CF_STRIDE;
            cfF[cb + jj]           = __float2half_rn(e0);
            cfF[cb + 20 + jj]      = __float2half_rn(e0 * ux);
            cfF[cb + 40 + jj]      = __float2half_rn(e0 * uy);
            cfF[cb + 60 + jj]      = __float2half_rn(e0 * uz);
            cfF[cb + jj + 10]      = __float2half_rn(e1);
            cfF[cb + 20 + jj + 10] = __float2half_rn(e1 * ux);
            cfF[cb + 40 + jj + 10] = __float2half_rn(e1 * uy);
            cfF[cb + 60 + jj + 10] = __float2half_rn(e1 * uz);
            __half2 h0a, h0b, h1a, h1b;
            h0a.x = __float2half_rn(fv0.x); h0a.y = __float2half_rn(fv0.y);
            h0b.x = __float2half_rn(fv0.z); h0b.y = __float2half_rn(fv0.w);
            h1a.x = __float2half_rn(fv1.x); h1a.y = __float2half_rn(fv1.y);
            h1b.x = __float2half_rn(fv1.z); h1b.y = __float2half_rn(fv1.w);
            *(__half2*)&ftF[cb + jj * 4]            = h0a;
            *(__half2*)&ftF[cb + jj * 4 + 2]        = h0b;
            *(__half2*)&ftF[cb + (jj + 10) * 4]     = h1a;
            *(__half2*)&ftF[cb + (jj + 10) * 4 + 2] = h1b;
        }
        __syncthreads();                    // tiles ready (single barrier per chunk)

        // prefetch chunk t+1 (overlaps consume)
        have = 0;
        if (t + 1 < T) {
            int at2 = cur_at;
            while (at2 < ATOMS_PER_BLK - 1 && t + 1 >= cum[at2 + 1]) at2++;
            int p = segs[at2] + (t + 1 - cum[at2]) * PCH + pp;
            if (p < segs[at2 + 1]) {
                nd = dist[p]; nx = coord[3 * p]; ny = coord[3 * p + 1]; nz = coord[3 * p + 2];
                int r = ps[p];
                nf0 = ((const float4*)feat)[r * 20 + jj];
                nf1 = ((const float4*)feat)[r * 20 + jj + 10];
                have = 1;
            }
        }

        // consume: 2 k16-steps, each ldsm.trans + 5 mma
        #pragma unroll
        for (int s = 0; s < 2; s++) {
            uint32_t sb2 = bofs + (uint32_t)(s * STEP_BYTES);
            unsigned aF[4], bF[10];
            ldsm4t(aF, uCfF + sb2 + aoff);
            ldsm4t(bF + 0, uFtF + sb2 + boff0);
            ldsm4t(bF + 4, uFtF + sb2 + boff1);
            ldsm2t(bF + 8, uFtF + sb2 + boff2);
            #pragma unroll
            for (int nt = 0; nt < 5; nt++)
                mma16816f(acc[nt], aF, bF + 2 * nt);
        }

        if (t == cum[cur_at + 1] - 1)
            flush_mma(acc, a0 + cur_at, cs0, f0w, lane);
    }

    #pragma unroll
    for (int i = 0; i < ATOMS_PER_BLK; i++)
        if (cum[i + 1] == cum[i])
            flush_mma(acc, a0 + i, cs0, f0w, lane);

    // self-interaction rows: env[(a,c), 1600+f] = (c==0) ? feat[a,f] : 0
    {
        int c2 = tid / 80;   // 0..3
        int f  = tid % 80;
        #pragma unroll
        for (int ai = 0; ai < ATOMS_PER_BLK; ai++) {
            int a = a0 + ai;
            float v = (c2 == 0) ? feat[a * 80 + f] : 0.0f;
            g_env_f16[(size_t)(a * 4 + c2) * KTOT + 1600 + f] = __float2half_rn(v);
        }
    }
}

// ---------------- K2: fp16 GEMM, single-plane A & B, 4-stage pipeline ----------
__device__ __forceinline__ void load_stage(uint32_t sstage, int m0, int kc, int tid) {
    #pragma unroll
    for (int i = 0; i < 2; i++) {
        int u = tid + i * 256;                 // 512: 64 rows x 8 segs
        int r = u >> 3, sg = u & 7;
        uint32_t so = (uint32_t)(r * 128 + ((sg ^ (r & 7)) * 16));
        const char* ga = (const char*)(g_env_f16 + (size_t)(m0 + r) * KTOT + kc) + sg * 16;
        CP16(sstage + OFF_AF + so, ga);
    }
    #pragma unroll
    for (int i = 0; i < 3; i++) {
        int u = tid + i * 256;                 // 640: 80 rows x 8 segs
        if (u < 640) {
            int r = u >> 3, sg = u & 7;
            uint32_t so = (uint32_t)(r * 128 + ((sg ^ (r & 7)) * 16));
            const char* gb = (const char*)(g_w2 + (size_t)r * KTOT + kc) + sg * 16;
            CP16(sstage + OFF_BH + so, gb);
        }
    }
}

__global__ __launch_bounds__(256, 2)
void gemm_kernel(const float* __restrict__ selfb, const float* __restrict__ vecs,
                 float* __restrict__ out, int n_atoms)
{
    extern __shared__ __align__(1024) char smem[];
    uint32_t sb = smem_u32(smem);
    int tid  = threadIdx.x;
    int lane = tid & 31;
    int wid  = tid >> 5;
    int m0   = blockIdx.x * BM64;

    int wg = wid >> 2;            // k-group: ks in {2*wg, 2*wg+1}
    int wi = wid & 3;
    int m0w = (wi >> 1) * 32;
    int n0w = (wi & 1) * 40;
    int ksBase = wg * 2;

    int rA_loc = (lane & 7) + ((lane >> 3) & 1) * 8;
    uint32_t rowA0 = (uint32_t)((m0w + rA_loc) * 128);
    uint32_t rowA1 = rowA0 + 16 * 128;
    int rB_loc = (lane & 7) + ((lane >> 4) & 1) * 8;
    uint32_t rowB0 = (uint32_t)((n0w + rB_loc) * 128);
    uint32_t rowB1 = rowB0 + 16 * 128;
    uint32_t rowB2 = (uint32_t)((n0w + 32 + (lane & 7)) * 128);

    float acc[2][5][4];
    #pragma unroll
    for (int mt = 0; mt < 2; mt++)
        #pragma unroll
        for (int nt = 0; nt < 5; nt++)
            #pragma unroll
            for (int q = 0; q < 4; q++) acc[mt][nt][q] = 0.0f;

    load_stage(sb, m0, 0, tid);                       CP_COMMIT();
    load_stage(sb + STG_BYTES, m0, KCH, tid);         CP_COMMIT();
    load_stage(sb + 2 * STG_BYTES, m0, 2 * KCH, tid); CP_COMMIT();
    load_stage(sb + 3 * STG_BYTES, m0, 3 * KCH, tid); CP_COMMIT();

    for (int c = 0; c < NCH; c++) {
        if (c < NCH - 3) CP_WAIT3();
        else if (c == NCH - 3) CP_WAIT2();
        else if (c == NCH - 2) CP_WAIT1();
        else CP_WAIT0();
        __syncthreads();

        uint32_t st  = sb + (uint32_t)((c % NSTAGE) * STG_BYTES);
        uint32_t sAF = st + OFF_AF;
        uint32_t sBH = st + OFF_BH;

        #pragma unroll
        for (int kss = 0; kss < 2; kss++) {
            int ks = ksBase + kss;
            uint32_t swA = (uint32_t)((((ks * 2) + (lane >> 4)) ^ (lane & 7)) * 16);
            uint32_t swB = (uint32_t)((((ks * 2) + ((lane >> 3) & 1)) ^ (lane & 7)) * 16);
            unsigned aF[2][4], bF[10];
            ldsm4(aF[0], sAF + rowA0 + swA);
            ldsm4(aF[1], sAF + rowA1 + swA);
            ldsm4(bF + 0, sBH + rowB0 + swB);
            ldsm4(bF + 4, sBH + rowB1 + swB);
            ldsm2(bF + 8, sBH + rowB2 + swB);
            #pragma unroll
            for (int mt = 0; mt < 2; mt++)
                #pragma unroll
                for (int nt = 0; nt < 5; nt++)
                    mma16816f(acc[mt][nt], aF[mt], bF + 2 * nt);
        }
        __syncthreads();
        if (c + 4 < NCH) {
            load_stage(sb + (uint32_t)((c % NSTAGE) * STG_BYTES), m0, (c + 4) * KCH, tid);
            CP_COMMIT();
        }
    }

    // merge k-split partials through C[64][80] in smem
    float* C = (float*)smem;
    int grp  = lane >> 2;
    int col0 = (lane & 3) * 2;
    if (wg == 1) {
        #pragma unroll
        for (int mt = 0; mt < 2; mt++) {
            int r0 = m0w + mt * 16 + grp;
            #pragma unroll
            for (int nt = 0; nt < 5; nt++) {
                int cc = n0w + nt * 8 + col0;
                *(float2*)&C[r0 * 80 + cc]       = make_float2(acc[mt][nt][0], acc[mt][nt][1]);
                *(float2*)&C[(r0 + 8) * 80 + cc] = make_float2(acc[mt][nt][2], acc[mt][nt][3]);
            }
        }
    }
    __syncthreads();
    if (wg == 0) {
        #pragma unroll
        for (int mt = 0; mt < 2; mt++) {
            int r0 = m0w + mt * 16 + grp;
            #pragma unroll
            for (int nt = 0; nt < 5; nt++) {
                int cc = n0w + nt * 8 + col0;
                float2 v0 = *(float2*)&C[r0 * 80 + cc];
                float2 v1 = *(float2*)&C[(r0 + 8) * 80 + cc];
                v0.x += acc[mt][nt][0]; v0.y += acc[mt][nt][1];
                v1.x += acc[mt][nt][2]; v1.y += acc[mt][nt][3];
                *(float2*)&C[r0 * 80 + cc]       = v0;
                *(float2*)&C[(r0 + 8) * 80 + cc] = v1;
            }
        }
    }
    __syncthreads();

    #pragma unroll
    for (int u = tid; u < 1280; u += 256) {
        int al = u / 80, o = u % 80;
        int a = (m0 >> 2) + al;
        if (a < n_atoms) {
            float s0 = C[(al * 4 + 0) * 80 + o];
            float x  = C[(al * 4 + 1) * 80 + o];
            float y  = C[(al * 4 + 2) * 80 + o];
            float z  = C[(al * 4 + 3) * 80 + o];
            out[a * 80 + o] = s0 + selfb[o]
                + vecs[o] * sqrtf(fmaf(x, x, fmaf(y, y, z * z)) + 1e-30f);
        }
    }
}

// ---------------- launch ----------------
extern "C" void kernel_launch(void* const* d_in, const int* in_sizes, int n_in,
                              void* d_out, int out_size) {
    const float* feat  = (const float*)d_in[0];
    const float* dist  = (const float*)d_in[1];
    const float* coord = (const float*)d_in[2];
    const float* iw    = (const float*)d_in[3];
    const float* selfw = (const float*)d_in[4];
    const float* selfb = (const float*)d_in[5];
    const float* vecs  = (const float*)d_in[6];
    const float* mu    = (const float*)d_in[7];
    const float* sigma = (const float*)d_in[8];
    const int*   pf    = (const int*)d_in[9];
    const int*   ps    = (const int*)d_in[10];
    int n_pairs = in_sizes[9];
    int n_atoms = in_sizes[0] / 80;
    float* out = (float*)d_out;

    static int smem_set = 0;
    if (!smem_set) {
        cudaFuncSetAttribute(gemm_kernel, cudaFuncAttributeMaxDynamicSharedMemorySize,
                             NSTAGE * STG_BYTES);
        smem_set = 1;
    }

    build_w_kernel<<<(80 * KTOT + 255) / 256, 256>>>(iw, selfw);
    seg_kernel<<<(n_atoms + 256) / 256, 256>>>(pf, n_pairs, n_atoms);
    envsum_kernel<<<n_atoms / ATOMS_PER_BLK, 320>>>(feat, dist, coord, mu, sigma, ps);
    int mtiles = (n_atoms * 4 + BM64 - 1) / BM64;
    gemm_kernel<<<mtiles, 256, NSTAGE * STG_BYTES>>>(selfb, vecs, out, n_atoms);
}